// round 1
// baseline (speedup 1.0000x reference)
#include <cuda_runtime.h>
#include <math.h>

#define BB 64
#define CC 768
#define LL 197
#define DEG1 4
#define C4 3072          // CC * DEG1
#define LP 199           // LL + 2 (zero-padded cols for conv)
#define NBL (BB*LL)      // 12608
#define EPSV 1e-5f

// ---------------- scratch (static device memory; no runtime allocs) ----------------
__device__ float g_z[(size_t)BB * C4 * LP];      // padded KACN basis  (~156 MB)
__device__ float g_q[(size_t)BB * CC * LL];
__device__ float g_k[(size_t)BB * CC * LL];
__device__ float g_v[(size_t)BB * CC * LL];
__device__ float g_Qr[(size_t)BB * LL * CC];
__device__ float g_Kr[(size_t)BB * LL * CC];
__device__ float g_att[(size_t)BB * LL * LL];
__device__ float g_y[(size_t)BB * CC * LL];
__device__ float g_coeff[4 * CC];                // BN fold: y = x*coeff + off  (slots q,k,v,final)
__device__ float g_off[4 * CC];

// ---------------- 1) KACN basis: z = T_m(tanh(x)), m=0..3, zero-padded in L ----------------
__global__ void build_z(const float* __restrict__ x) {
    int idx = blockIdx.x * blockDim.x + threadIdx.x;
    if (idx >= BB * CC * LL) return;
    int l = idx % LL;
    int bc = idx / LL;
    int c = bc % CC;
    int b = bc / CC;
    float t  = tanhf(x[idx]);
    float t2 = 2.f * t * t - 1.f;        // T2
    float t3 = 2.f * t * t2 - t;         // T3
    size_t base = ((size_t)b * C4 + (size_t)c * 4) * LP;
    g_z[base + 0 * LP + l + 1] = 1.f;
    g_z[base + 1 * LP + l + 1] = t;
    g_z[base + 2 * LP + l + 1] = t2;
    g_z[base + 3 * LP + l + 1] = t3;
    if (l == 0) {
        #pragma unroll
        for (int m = 0; m < 4; m++) {
            g_z[base + m * LP + 0]      = 0.f;
            g_z[base + m * LP + LL + 1] = 0.f;
        }
    }
}

// ---------------- 2) conv1d as GEMM: out[b,co,l] = sum_{ci,k} W[co,ci,k] * zpad[b,ci,l+k] ----------------
// BM=128 (co), BN=128 (l), BK=8 (ci). 256 threads, 8x8 microtile, 3 taps folded.
__global__ void __launch_bounds__(256)
conv_gemm(const float* __restrict__ Wq, const float* __restrict__ Wk, const float* __restrict__ Wv) {
    const int BM = 128, BN = 128, BK = 8;
    int which = blockIdx.z / BB;          // 0=q 1=k 2=v
    int b     = blockIdx.z % BB;
    int m0 = blockIdx.y * BM;
    int n0 = blockIdx.x * BN;

    const float* W = (which == 0) ? Wq : (which == 1) ? Wk : Wv;
    float* out = ((which == 0) ? g_q : (which == 1) ? g_k : g_v) + (size_t)b * CC * LL;
    const float* zb = g_z + (size_t)b * C4 * LP;

    __shared__ float As[3][BK][BM];        // 12 KB
    __shared__ float Bs[BK][BN + 4];       // 8x132 = 4.2 KB

    int tid = threadIdx.x;
    int tn = tid & 15, tm = tid >> 4;

    float acc[8][8];
    #pragma unroll
    for (int m = 0; m < 8; m++)
        #pragma unroll
        for (int j = 0; j < 8; j++) acc[m][j] = 0.f;

    for (int k0 = 0; k0 < C4; k0 += BK) {
        // ---- load A tile: W[m0..m0+127, k0..k0+7, 0..2]  (3072 floats)
        {
            int co  = tid >> 1;
            int off = (tid & 1) * 12;
            const float* wp = W + (size_t)(m0 + co) * (C4 * 3) + (size_t)k0 * 3 + off;
            #pragma unroll
            for (int u = 0; u < 12; u++) {
                int q = off + u;
                As[q % 3][q / 3][co] = wp[u];
            }
        }
        // ---- load B tile: zpad[k0..k0+7, n0 .. n0+129]
        for (int idx = tid; idx < BK * (BN + 2); idx += 256) {
            int r = idx / (BN + 2);
            int jcol = idx - r * (BN + 2);
            int col = n0 + jcol;
            float v = 0.f;
            if (col < LP) v = zb[(size_t)(k0 + r) * LP + col];
            Bs[r][jcol] = v;
        }
        __syncthreads();

        #pragma unroll
        for (int kk = 0; kk < BK; kk++) {
            float br[10];
            {
                float4 b0 = *reinterpret_cast<const float4*>(&Bs[kk][tn * 8]);
                float4 b1 = *reinterpret_cast<const float4*>(&Bs[kk][tn * 8 + 4]);
                br[0]=b0.x; br[1]=b0.y; br[2]=b0.z; br[3]=b0.w;
                br[4]=b1.x; br[5]=b1.y; br[6]=b1.z; br[7]=b1.w;
                br[8]=Bs[kk][tn*8+8]; br[9]=Bs[kk][tn*8+9];
            }
            float a0[8], a1[8], a2[8];
            {
                float4 p, q;
                p = *reinterpret_cast<const float4*>(&As[0][kk][tm*8]);
                q = *reinterpret_cast<const float4*>(&As[0][kk][tm*8+4]);
                a0[0]=p.x;a0[1]=p.y;a0[2]=p.z;a0[3]=p.w;a0[4]=q.x;a0[5]=q.y;a0[6]=q.z;a0[7]=q.w;
                p = *reinterpret_cast<const float4*>(&As[1][kk][tm*8]);
                q = *reinterpret_cast<const float4*>(&As[1][kk][tm*8+4]);
                a1[0]=p.x;a1[1]=p.y;a1[2]=p.z;a1[3]=p.w;a1[4]=q.x;a1[5]=q.y;a1[6]=q.z;a1[7]=q.w;
                p = *reinterpret_cast<const float4*>(&As[2][kk][tm*8]);
                q = *reinterpret_cast<const float4*>(&As[2][kk][tm*8+4]);
                a2[0]=p.x;a2[1]=p.y;a2[2]=p.z;a2[3]=p.w;a2[4]=q.x;a2[5]=q.y;a2[6]=q.z;a2[7]=q.w;
            }
            #pragma unroll
            for (int m = 0; m < 8; m++) {
                #pragma unroll
                for (int j = 0; j < 8; j++) {
                    acc[m][j] += a0[m]*br[j] + a1[m]*br[j+1] + a2[m]*br[j+2];
                }
            }
        }
        __syncthreads();
    }

    #pragma unroll
    for (int m = 0; m < 8; m++) {
        int co = m0 + tm * 8 + m;
        #pragma unroll
        for (int j = 0; j < 8; j++) {
            int l = n0 + tn * 8 + j;
            if (l < LL) out[(size_t)co * LL + l] = acc[m][j];
        }
    }
}

// ---------------- 3) BN stats over (B,L) per channel -> folded coeff/off ----------------
__global__ void bn_stats(int sel, const float* __restrict__ scale, const float* __restrict__ bias) {
    const float* in = (sel == 0) ? g_q : (sel == 1) ? g_k : (sel == 2) ? g_v : g_y;
    int c = blockIdx.x;
    float s = 0.f, s2 = 0.f;
    for (int i = threadIdx.x; i < NBL; i += 256) {
        int b = i / LL, l = i - b * LL;
        float v = in[((size_t)b * CC + c) * LL + l];
        s += v; s2 += v * v;
    }
    __shared__ float sh[256], sh2[256];
    sh[threadIdx.x] = s; sh2[threadIdx.x] = s2;
    __syncthreads();
    for (int st = 128; st > 0; st >>= 1) {
        if (threadIdx.x < st) { sh[threadIdx.x] += sh[threadIdx.x + st]; sh2[threadIdx.x] += sh2[threadIdx.x + st]; }
        __syncthreads();
    }
    if (threadIdx.x == 0) {
        float m = sh[0] / (float)NBL;
        float var = sh2[0] / (float)NBL - m * m;
        float cf = scale[c] * rsqrtf(var + EPSV);
        g_coeff[sel * CC + c] = cf;
        g_off[sel * CC + c]   = bias[c] - m * cf;
    }
}

// ---------------- 4) BN + transpose + RoPE for Q,K ----------------
__global__ void rope_kernel(const float* __restrict__ freqs) {
    int b  = blockIdx.z;
    int c0 = blockIdx.y * 64;
    int l0 = blockIdx.x * 32;
    __shared__ float s[64][33];
    for (int which = 0; which < 2; which++) {
        const float* src = which ? g_k : g_q;
        const float* cf  = g_coeff + which * CC;
        const float* of  = g_off   + which * CC;
        float* dst = which ? g_Kr : g_Qr;
        for (int t = threadIdx.x; t < 64 * 32; t += 256) {
            int cl = t / 32, ll = t - cl * 32;
            int c = c0 + cl, l = l0 + ll;
            float v = 0.f;
            if (l < LL) v = src[((size_t)b * CC + c) * LL + l] * cf[c] + of[c];
            s[cl][ll] = v;
        }
        __syncthreads();
        for (int t = threadIdx.x; t < 32 * 32; t += 256) {
            int ll = t / 32, dl = t - ll * 32;
            int l = l0 + ll;
            if (l < LL) {
                int d = c0 / 2 + dl;
                float a  = s[2 * dl][ll];
                float bb = s[2 * dl + 1][ll];
                float ra, rb;
                if (l == 0) { ra = a; rb = bb; }
                else {
                    float nf = (float)(l - 1);
                    float tx = fmodf(nf, 14.0f);
                    float ty = floorf(nf / 14.0f);
                    float ang = tx * freqs[d] + ty * freqs[384 + d];
                    float sn, cs;
                    sincosf(ang, &sn, &cs);
                    ra = a * cs - bb * sn;
                    rb = a * sn + bb * cs;
                }
                size_t o = ((size_t)b * LL + l) * CC + c0 + 2 * dl;
                dst[o] = ra; dst[o + 1] = rb;
            }
        }
        __syncthreads();
    }
}

// ---------------- 5) energy[b,i,j] = <Qr[b,i,:], Kr[b,j,:]> ----------------
__global__ void energy_gemm() {
    int b = blockIdx.z;
    int i0 = blockIdx.y * 64, j0 = blockIdx.x * 64;
    __shared__ float As[16][68], Bs[16][68];
    const float* Qb = g_Qr + (size_t)b * LL * CC;
    const float* Kb = g_Kr + (size_t)b * LL * CC;
    int tid = threadIdx.x;
    int tm = tid / 16, tn = tid & 15;
    float acc[4][4];
    #pragma unroll
    for (int m = 0; m < 4; m++) for (int n = 0; n < 4; n++) acc[m][n] = 0.f;

    int r = tid >> 2, u = tid & 3;
    for (int k0 = 0; k0 < CC; k0 += 16) {
        float4 qv = make_float4(0,0,0,0), kv = make_float4(0,0,0,0);
        if (i0 + r < LL) qv = *reinterpret_cast<const float4*>(Qb + (size_t)(i0 + r) * CC + k0 + u * 4);
        if (j0 + r < LL) kv = *reinterpret_cast<const float4*>(Kb + (size_t)(j0 + r) * CC + k0 + u * 4);
        As[u*4+0][r]=qv.x; As[u*4+1][r]=qv.y; As[u*4+2][r]=qv.z; As[u*4+3][r]=qv.w;
        Bs[u*4+0][r]=kv.x; Bs[u*4+1][r]=kv.y; Bs[u*4+2][r]=kv.z; Bs[u*4+3][r]=kv.w;
        __syncthreads();
        #pragma unroll
        for (int kk = 0; kk < 16; kk++) {
            float4 a4 = *reinterpret_cast<const float4*>(&As[kk][tm * 4]);
            float4 b4 = *reinterpret_cast<const float4*>(&Bs[kk][tn * 4]);
            float a[4] = {a4.x, a4.y, a4.z, a4.w};
            float bb[4] = {b4.x, b4.y, b4.z, b4.w};
            #pragma unroll
            for (int m = 0; m < 4; m++)
                #pragma unroll
                for (int n = 0; n < 4; n++) acc[m][n] += a[m] * bb[n];
        }
        __syncthreads();
    }
    #pragma unroll
    for (int m = 0; m < 4; m++) {
        int i = i0 + tm * 4 + m;
        #pragma unroll
        for (int n = 0; n < 4; n++) {
            int j = j0 + tn * 4 + n;
            if (i < LL && j < LL) g_att[((size_t)b * LL + i) * LL + j] = acc[m][n];
        }
    }
}

// ---------------- 6) softmax over j (in place) ----------------
__global__ void softmax_kernel() {
    int row = blockIdx.x * blockDim.y + threadIdx.y;
    if (row >= NBL) return;
    float* e = g_att + (size_t)row * LL;
    int lane = threadIdx.x;
    float mx = -1e30f;
    for (int j = lane; j < LL; j += 32) mx = fmaxf(mx, e[j]);
    #pragma unroll
    for (int o = 16; o; o >>= 1) mx = fmaxf(mx, __shfl_xor_sync(0xffffffffu, mx, o));
    float s = 0.f;
    for (int j = lane; j < LL; j += 32) { float v = __expf(e[j] - mx); e[j] = v; s += v; }
    #pragma unroll
    for (int o = 16; o; o >>= 1) s += __shfl_xor_sync(0xffffffffu, s, o);
    float inv = 1.f / s;
    for (int j = lane; j < LL; j += 32) e[j] *= inv;
}

// ---------------- 7) out[b,c,i] = sum_j vbn[b,c,j]*att[b,i,j]; y = gamma*x + out ----------------
__global__ void out_gemm(const float* __restrict__ x, const float* __restrict__ gamma) {
    int b = blockIdx.z;
    int c0 = blockIdx.y * 64, i0 = blockIdx.x * 64;
    __shared__ float As[16][68], Bs[16][68];
    int tid = threadIdx.x;
    int tm = tid / 16, tn = tid & 15;
    float acc[4][4];
    #pragma unroll
    for (int m = 0; m < 4; m++) for (int n = 0; n < 4; n++) acc[m][n] = 0.f;

    int r = tid >> 2, u = tid & 3;
    const float* vb = g_v + (size_t)b * CC * LL;
    const float* ab = g_att + (size_t)b * LL * LL;
    int cA = c0 + r;
    float cf = g_coeff[2 * CC + cA];
    float of = g_off[2 * CC + cA];

    for (int k0 = 0; k0 < LL; k0 += 16) {
        #pragma unroll
        for (int w = 0; w < 4; w++) {
            int j = k0 + u * 4 + w;
            float av = 0.f, bv = 0.f;
            if (j < LL) {
                av = vb[(size_t)cA * LL + j] * cf + of;
                if (i0 + r < LL) bv = ab[(size_t)(i0 + r) * LL + j];
            }
            As[u*4+w][r] = av;
            Bs[u*4+w][r] = bv;
        }
        __syncthreads();
        #pragma unroll
        for (int kk = 0; kk < 16; kk++) {
            float4 a4 = *reinterpret_cast<const float4*>(&As[kk][tm * 4]);
            float4 b4 = *reinterpret_cast<const float4*>(&Bs[kk][tn * 4]);
            float a[4] = {a4.x, a4.y, a4.z, a4.w};
            float bb[4] = {b4.x, b4.y, b4.z, b4.w};
            #pragma unroll
            for (int m = 0; m < 4; m++)
                #pragma unroll
                for (int n = 0; n < 4; n++) acc[m][n] += a[m] * bb[n];
        }
        __syncthreads();
    }
    float g0 = gamma[0];
    #pragma unroll
    for (int m = 0; m < 4; m++) {
        int c = c0 + tm * 4 + m;
        #pragma unroll
        for (int n = 0; n < 4; n++) {
            int i = i0 + tn * 4 + n;
            if (i < LL) {
                size_t o = ((size_t)b * CC + c) * LL + i;
                g_y[o] = g0 * x[o] + acc[m][n];
            }
        }
    }
}

// ---------------- 8) final normalize to output ----------------
__global__ void final_norm(float* __restrict__ out) {
    int idx = blockIdx.x * blockDim.x + threadIdx.x;
    if (idx >= BB * CC * LL) return;
    int c = (idx / LL) % CC;
    out[idx] = g_y[idx] * g_coeff[3 * CC + c] + g_off[3 * CC + c];
}

// ---------------- launch ----------------
extern "C" void kernel_launch(void* const* d_in, const int* in_sizes, int n_in,
                              void* d_out, int out_size) {
    const float* x      = (const float*)d_in[0];
    const float* Wq     = (const float*)d_in[1];
    const float* Wk     = (const float*)d_in[2];
    const float* Wv     = (const float*)d_in[3];
    const float* bnq_s  = (const float*)d_in[4];
    const float* bnq_b  = (const float*)d_in[5];
    const float* bnk_s  = (const float*)d_in[6];
    const float* bnk_b  = (const float*)d_in[7];
    const float* bnv_s  = (const float*)d_in[8];
    const float* bnv_b  = (const float*)d_in[9];
    const float* gamma  = (const float*)d_in[10];
    const float* freqs  = (const float*)d_in[11];
    const float* norm_s = (const float*)d_in[12];
    const float* norm_b = (const float*)d_in[13];
    float* out = (float*)d_out;

    build_z<<<(BB * CC * LL + 255) / 256, 256>>>(x);
    conv_gemm<<<dim3(2, 6, 3 * BB), 256>>>(Wq, Wk, Wv);
    bn_stats<<<CC, 256>>>(0, bnq_s, bnq_b);
    bn_stats<<<CC, 256>>>(1, bnk_s, bnk_b);
    bn_stats<<<CC, 256>>>(2, bnv_s, bnv_b);
    rope_kernel<<<dim3(7, 12, BB), 256>>>(freqs);
    energy_gemm<<<dim3(4, 4, BB), 256>>>();
    softmax_kernel<<<dim3((NBL + 3) / 4), dim3(32, 4)>>>();
    out_gemm<<<dim3(4, 12, BB), 256>>>(x, gamma);
    bn_stats<<<CC, 256>>>(3, norm_s, norm_b);
    final_norm<<<(BB * CC * LL + 255) / 256, 256>>>(out);
}

// round 2
// speedup vs baseline: 1.0002x; 1.0002x over previous
#include <cuda_runtime.h>
#include <math.h>

#define BB 64
#define CC 768
#define LL 197
#define DEG1 4
#define C4 3072          // CC * DEG1
#define LP 199           // LL + 2 (zero-padded cols for conv)
#define NBL (BB*LL)      // 12608
#define EPSV 1e-5f

// ---------------- scratch (static device memory; no runtime allocs) ----------------
__device__ float g_z[(size_t)BB * C4 * LP];      // padded KACN basis  (~156 MB)
__device__ float g_q[(size_t)BB * CC * LL];
__device__ float g_k[(size_t)BB * CC * LL];
__device__ float g_v[(size_t)BB * CC * LL];
__device__ float g_Qr[(size_t)BB * LL * CC];
__device__ float g_Kr[(size_t)BB * LL * CC];
__device__ float g_att[(size_t)BB * LL * LL];
__device__ float g_y[(size_t)BB * CC * LL];
__device__ float g_coeff[4 * CC];                // BN fold: y = x*coeff + off  (slots q,k,v,final)
__device__ float g_off[4 * CC];

// ---------------- 1) KACN basis: z = T_m(tanh(x)), m=0..3, zero-padded in L ----------------
__global__ void build_z(const float* __restrict__ x) {
    int idx = blockIdx.x * blockDim.x + threadIdx.x;
    if (idx >= BB * CC * LL) return;
    int l = idx % LL;
    int bc = idx / LL;
    int c = bc % CC;
    int b = bc / CC;
    float t  = tanhf(x[idx]);
    float t2 = 2.f * t * t - 1.f;        // T2
    float t3 = 2.f * t * t2 - t;         // T3
    size_t base = ((size_t)b * C4 + (size_t)c * 4) * LP;
    g_z[base + 0 * LP + l + 1] = 1.f;
    g_z[base + 1 * LP + l + 1] = t;
    g_z[base + 2 * LP + l + 1] = t2;
    g_z[base + 3 * LP + l + 1] = t3;
    if (l == 0) {
        #pragma unroll
        for (int m = 0; m < 4; m++) {
            g_z[base + m * LP + 0]      = 0.f;
            g_z[base + m * LP + LL + 1] = 0.f;
        }
    }
}

// ---------------- 2) conv1d as GEMM: out[b,co,l] = sum_{ci,k} W[co,ci,k] * zpad[b,ci,l+k] ----------------
// BM=128 (co), BN=128 (l), BK=8 (ci). 256 threads, 8x8 microtile, 3 taps folded.
__global__ void __launch_bounds__(256)
conv_gemm(const float* __restrict__ Wq, const float* __restrict__ Wk, const float* __restrict__ Wv) {
    const int BM = 128, BN = 128, BK = 8;
    int which = blockIdx.z / BB;          // 0=q 1=k 2=v
    int b     = blockIdx.z % BB;
    int m0 = blockIdx.y * BM;
    int n0 = blockIdx.x * BN;

    const float* W = (which == 0) ? Wq : (which == 1) ? Wk : Wv;
    float* out = ((which == 0) ? g_q : (which == 1) ? g_k : g_v) + (size_t)b * CC * LL;
    const float* zb = g_z + (size_t)b * C4 * LP;

    __shared__ float As[3][BK][BM];        // 12 KB
    __shared__ float Bs[BK][BN + 4];       // 8x132 = 4.2 KB

    int tid = threadIdx.x;
    int tn = tid & 15, tm = tid >> 4;

    float acc[8][8];
    #pragma unroll
    for (int m = 0; m < 8; m++)
        #pragma unroll
        for (int j = 0; j < 8; j++) acc[m][j] = 0.f;

    for (int k0 = 0; k0 < C4; k0 += BK) {
        // ---- load A tile: W[m0..m0+127, k0..k0+7, 0..2]  (3072 floats)
        {
            int co  = tid >> 1;
            int off = (tid & 1) * 12;
            const float* wp = W + (size_t)(m0 + co) * (C4 * 3) + (size_t)k0 * 3 + off;
            #pragma unroll
            for (int u = 0; u < 12; u++) {
                int q = off + u;
                As[q % 3][q / 3][co] = wp[u];
            }
        }
        // ---- load B tile: zpad[k0..k0+7, n0 .. n0+129]
        for (int idx = tid; idx < BK * (BN + 2); idx += 256) {
            int r = idx / (BN + 2);
            int jcol = idx - r * (BN + 2);
            int col = n0 + jcol;
            float v = 0.f;
            if (col < LP) v = zb[(size_t)(k0 + r) * LP + col];
            Bs[r][jcol] = v;
        }
        __syncthreads();

        #pragma unroll
        for (int kk = 0; kk < BK; kk++) {
            float br[10];
            {
                float4 b0 = *reinterpret_cast<const float4*>(&Bs[kk][tn * 8]);
                float4 b1 = *reinterpret_cast<const float4*>(&Bs[kk][tn * 8 + 4]);
                br[0]=b0.x; br[1]=b0.y; br[2]=b0.z; br[3]=b0.w;
                br[4]=b1.x; br[5]=b1.y; br[6]=b1.z; br[7]=b1.w;
                br[8]=Bs[kk][tn*8+8]; br[9]=Bs[kk][tn*8+9];
            }
            float a0[8], a1[8], a2[8];
            {
                float4 p, q;
                p = *reinterpret_cast<const float4*>(&As[0][kk][tm*8]);
                q = *reinterpret_cast<const float4*>(&As[0][kk][tm*8+4]);
                a0[0]=p.x;a0[1]=p.y;a0[2]=p.z;a0[3]=p.w;a0[4]=q.x;a0[5]=q.y;a0[6]=q.z;a0[7]=q.w;
                p = *reinterpret_cast<const float4*>(&As[1][kk][tm*8]);
                q = *reinterpret_cast<const float4*>(&As[1][kk][tm*8+4]);
                a1[0]=p.x;a1[1]=p.y;a1[2]=p.z;a1[3]=p.w;a1[4]=q.x;a1[5]=q.y;a1[6]=q.z;a1[7]=q.w;
                p = *reinterpret_cast<const float4*>(&As[2][kk][tm*8]);
                q = *reinterpret_cast<const float4*>(&As[2][kk][tm*8+4]);
                a2[0]=p.x;a2[1]=p.y;a2[2]=p.z;a2[3]=p.w;a2[4]=q.x;a2[5]=q.y;a2[6]=q.z;a2[7]=q.w;
            }
            #pragma unroll
            for (int m = 0; m < 8; m++) {
                #pragma unroll
                for (int j = 0; j < 8; j++) {
                    acc[m][j] += a0[m]*br[j] + a1[m]*br[j+1] + a2[m]*br[j+2];
                }
            }
        }
        __syncthreads();
    }

    #pragma unroll
    for (int m = 0; m < 8; m++) {
        int co = m0 + tm * 8 + m;
        #pragma unroll
        for (int j = 0; j < 8; j++) {
            int l = n0 + tn * 8 + j;
            if (l < LL) out[(size_t)co * LL + l] = acc[m][j];
        }
    }
}

// ---------------- 3) BN stats over (B,L) per channel -> folded coeff/off ----------------
__global__ void bn_stats(int sel, const float* __restrict__ scale, const float* __restrict__ bias) {
    const float* in = (sel == 0) ? g_q : (sel == 1) ? g_k : (sel == 2) ? g_v : g_y;
    int c = blockIdx.x;
    float s = 0.f, s2 = 0.f;
    for (int i = threadIdx.x; i < NBL; i += 256) {
        int b = i / LL, l = i - b * LL;
        float v = in[((size_t)b * CC + c) * LL + l];
        s += v; s2 += v * v;
    }
    __shared__ float sh[256], sh2[256];
    sh[threadIdx.x] = s; sh2[threadIdx.x] = s2;
    __syncthreads();
    for (int st = 128; st > 0; st >>= 1) {
        if (threadIdx.x < st) { sh[threadIdx.x] += sh[threadIdx.x + st]; sh2[threadIdx.x] += sh2[threadIdx.x + st]; }
        __syncthreads();
    }
    if (threadIdx.x == 0) {
        float m = sh[0] / (float)NBL;
        float var = sh2[0] / (float)NBL - m * m;
        float cf = scale[c] * rsqrtf(var + EPSV);
        g_coeff[sel * CC + c] = cf;
        g_off[sel * CC + c]   = bias[c] - m * cf;
    }
}

// ---------------- 4) BN + transpose + RoPE for Q,K ----------------
__global__ void rope_kernel(const float* __restrict__ freqs) {
    int b  = blockIdx.z;
    int c0 = blockIdx.y * 64;
    int l0 = blockIdx.x * 32;
    __shared__ float s[64][33];
    for (int which = 0; which < 2; which++) {
        const float* src = which ? g_k : g_q;
        const float* cf  = g_coeff + which * CC;
        const float* of  = g_off   + which * CC;
        float* dst = which ? g_Kr : g_Qr;
        for (int t = threadIdx.x; t < 64 * 32; t += 256) {
            int cl = t / 32, ll = t - cl * 32;
            int c = c0 + cl, l = l0 + ll;
            float v = 0.f;
            if (l < LL) v = src[((size_t)b * CC + c) * LL + l] * cf[c] + of[c];
            s[cl][ll] = v;
        }
        __syncthreads();
        for (int t = threadIdx.x; t < 32 * 32; t += 256) {
            int ll = t / 32, dl = t - ll * 32;
            int l = l0 + ll;
            if (l < LL) {
                int d = c0 / 2 + dl;
                float a  = s[2 * dl][ll];
                float bb = s[2 * dl + 1][ll];
                float ra, rb;
                if (l == 0) { ra = a; rb = bb; }
                else {
                    float nf = (float)(l - 1);
                    float tx = fmodf(nf, 14.0f);
                    float ty = floorf(nf / 14.0f);
                    float ang = tx * freqs[d] + ty * freqs[384 + d];
                    float sn, cs;
                    sincosf(ang, &sn, &cs);
                    ra = a * cs - bb * sn;
                    rb = a * sn + bb * cs;
                }
                size_t o = ((size_t)b * LL + l) * CC + c0 + 2 * dl;
                dst[o] = ra; dst[o + 1] = rb;
            }
        }
        __syncthreads();
    }
}

// ---------------- 5) energy[b,i,j] = <Qr[b,i,:], Kr[b,j,:]> ----------------
__global__ void energy_gemm() {
    int b = blockIdx.z;
    int i0 = blockIdx.y * 64, j0 = blockIdx.x * 64;
    __shared__ float As[16][68], Bs[16][68];
    const float* Qb = g_Qr + (size_t)b * LL * CC;
    const float* Kb = g_Kr + (size_t)b * LL * CC;
    int tid = threadIdx.x;
    int tm = tid / 16, tn = tid & 15;
    float acc[4][4];
    #pragma unroll
    for (int m = 0; m < 4; m++) for (int n = 0; n < 4; n++) acc[m][n] = 0.f;

    int r = tid >> 2, u = tid & 3;
    for (int k0 = 0; k0 < CC; k0 += 16) {
        float4 qv = make_float4(0,0,0,0), kv = make_float4(0,0,0,0);
        if (i0 + r < LL) qv = *reinterpret_cast<const float4*>(Qb + (size_t)(i0 + r) * CC + k0 + u * 4);
        if (j0 + r < LL) kv = *reinterpret_cast<const float4*>(Kb + (size_t)(j0 + r) * CC + k0 + u * 4);
        As[u*4+0][r]=qv.x; As[u*4+1][r]=qv.y; As[u*4+2][r]=qv.z; As[u*4+3][r]=qv.w;
        Bs[u*4+0][r]=kv.x; Bs[u*4+1][r]=kv.y; Bs[u*4+2][r]=kv.z; Bs[u*4+3][r]=kv.w;
        __syncthreads();
        #pragma unroll
        for (int kk = 0; kk < 16; kk++) {
            float4 a4 = *reinterpret_cast<const float4*>(&As[kk][tm * 4]);
            float4 b4 = *reinterpret_cast<const float4*>(&Bs[kk][tn * 4]);
            float a[4] = {a4.x, a4.y, a4.z, a4.w};
            float bb[4] = {b4.x, b4.y, b4.z, b4.w};
            #pragma unroll
            for (int m = 0; m < 4; m++)
                #pragma unroll
                for (int n = 0; n < 4; n++) acc[m][n] += a[m] * bb[n];
        }
        __syncthreads();
    }
    #pragma unroll
    for (int m = 0; m < 4; m++) {
        int i = i0 + tm * 4 + m;
        #pragma unroll
        for (int n = 0; n < 4; n++) {
            int j = j0 + tn * 4 + n;
            if (i < LL && j < LL) g_att[((size_t)b * LL + i) * LL + j] = acc[m][n];
        }
    }
}

// ---------------- 6) softmax over j (in place) ----------------
__global__ void softmax_kernel() {
    int row = blockIdx.x * blockDim.y + threadIdx.y;
    if (row >= NBL) return;
    float* e = g_att + (size_t)row * LL;
    int lane = threadIdx.x;
    float mx = -1e30f;
    for (int j = lane; j < LL; j += 32) mx = fmaxf(mx, e[j]);
    #pragma unroll
    for (int o = 16; o; o >>= 1) mx = fmaxf(mx, __shfl_xor_sync(0xffffffffu, mx, o));
    float s = 0.f;
    for (int j = lane; j < LL; j += 32) { float v = __expf(e[j] - mx); e[j] = v; s += v; }
    #pragma unroll
    for (int o = 16; o; o >>= 1) s += __shfl_xor_sync(0xffffffffu, s, o);
    float inv = 1.f / s;
    for (int j = lane; j < LL; j += 32) e[j] *= inv;
}

// ---------------- 7) out[b,c,i] = sum_j vbn[b,c,j]*att[b,i,j]; y = gamma*x + out ----------------
__global__ void out_gemm(const float* __restrict__ x, const float* __restrict__ gamma) {
    int b = blockIdx.z;
    int c0 = blockIdx.y * 64, i0 = blockIdx.x * 64;
    __shared__ float As[16][68], Bs[16][68];
    int tid = threadIdx.x;
    int tm = tid / 16, tn = tid & 15;
    float acc[4][4];
    #pragma unroll
    for (int m = 0; m < 4; m++) for (int n = 0; n < 4; n++) acc[m][n] = 0.f;

    int r = tid >> 2, u = tid & 3;
    const float* vb = g_v + (size_t)b * CC * LL;
    const float* ab = g_att + (size_t)b * LL * LL;
    int cA = c0 + r;
    float cf = g_coeff[2 * CC + cA];
    float of = g_off[2 * CC + cA];

    for (int k0 = 0; k0 < LL; k0 += 16) {
        #pragma unroll
        for (int w = 0; w < 4; w++) {
            int j = k0 + u * 4 + w;
            float av = 0.f, bv = 0.f;
            if (j < LL) {
                av = vb[(size_t)cA * LL + j] * cf + of;
                if (i0 + r < LL) bv = ab[(size_t)(i0 + r) * LL + j];
            }
            As[u*4+w][r] = av;
            Bs[u*4+w][r] = bv;
        }
        __syncthreads();
        #pragma unroll
        for (int kk = 0; kk < 16; kk++) {
            float4 a4 = *reinterpret_cast<const float4*>(&As[kk][tm * 4]);
            float4 b4 = *reinterpret_cast<const float4*>(&Bs[kk][tn * 4]);
            float a[4] = {a4.x, a4.y, a4.z, a4.w};
            float bb[4] = {b4.x, b4.y, b4.z, b4.w};
            #pragma unroll
            for (int m = 0; m < 4; m++)
                #pragma unroll
                for (int n = 0; n < 4; n++) acc[m][n] += a[m] * bb[n];
        }
        __syncthreads();
    }
    float g0 = gamma[0];
    #pragma unroll
    for (int m = 0; m < 4; m++) {
        int c = c0 + tm * 4 + m;
        #pragma unroll
        for (int n = 0; n < 4; n++) {
            int i = i0 + tn * 4 + n;
            if (i < LL) {
                size_t o = ((size_t)b * CC + c) * LL + i;
                g_y[o] = g0 * x[o] + acc[m][n];
            }
        }
    }
}

// ---------------- 8) final normalize to output ----------------
__global__ void final_norm(float* __restrict__ out) {
    int idx = blockIdx.x * blockDim.x + threadIdx.x;
    if (idx >= BB * CC * LL) return;
    int c = (idx / LL) % CC;
    out[idx] = g_y[idx] * g_coeff[3 * CC + c] + g_off[3 * CC + c];
}

// ---------------- launch ----------------
extern "C" void kernel_launch(void* const* d_in, const int* in_sizes, int n_in,
                              void* d_out, int out_size) {
    const float* x      = (const float*)d_in[0];
    const float* Wq     = (const float*)d_in[1];
    const float* Wk     = (const float*)d_in[2];
    const float* Wv     = (const float*)d_in[3];
    const float* bnq_s  = (const float*)d_in[4];
    const float* bnq_b  = (const float*)d_in[5];
    const float* bnk_s  = (const float*)d_in[6];
    const float* bnk_b  = (const float*)d_in[7];
    const float* bnv_s  = (const float*)d_in[8];
    const float* bnv_b  = (const float*)d_in[9];
    const float* gamma  = (const float*)d_in[10];
    const float* freqs  = (const float*)d_in[11];
    const float* norm_s = (const float*)d_in[12];
    const float* norm_b = (const float*)d_in[13];
    float* out = (float*)d_out;

    build_z<<<(BB * CC * LL + 255) / 256, 256>>>(x);
    conv_gemm<<<dim3(2, 6, 3 * BB), 256>>>(Wq, Wk, Wv);
    bn_stats<<<CC, 256>>>(0, bnq_s, bnq_b);
    bn_stats<<<CC, 256>>>(1, bnk_s, bnk_b);
    bn_stats<<<CC, 256>>>(2, bnv_s, bnv_b);
    rope_kernel<<<dim3(7, 12, BB), 256>>>(freqs);
    energy_gemm<<<dim3(4, 4, BB), 256>>>();
    softmax_kernel<<<dim3((NBL + 3) / 4), dim3(32, 4)>>>();
    out_gemm<<<dim3(4, 12, BB), 256>>>(x, gamma);
    bn_stats<<<CC, 256>>>(3, norm_s, norm_b);
    final_norm<<<(BB * CC * LL + 255) / 256, 256>>>(out);
}

// round 4
// speedup vs baseline: 4.6438x; 4.6427x over previous
#include <cuda_runtime.h>
#include <cuda_bf16.h>
#include <math.h>
#include <stdint.h>

#define BB 64
#define CC 768
#define LL 197
#define NBL (BB*LL)
#define EPSV 1e-5f

// fused conv-GEMM geometry
#define MDIM 2304          // 3 proj * 768
#define KDIM 9216          // 3 taps * 3072
#define NROW 200           // padded rows per batch in zT
#define NP   (BB*NROW)     // 12800
#define NZROWS (NP+4)
#define NCHUNK 288         // KDIM/32
#define BKE 32
#define RSTRIDE 80         // smem row stride bytes (64B data + 16B pad, conflict-free)
#define A_BYTES (128*RSTRIDE)         // 10240
#define B_BYTES (256*RSTRIDE)         // 20480
#define STG_BYTES (2*A_BYTES + 2*B_BYTES)  // 61440
#define SMEMSZ (3*STG_BYTES)               // 184320

// ---------------- static device scratch ----------------
__device__ __nv_bfloat16 g_zhi[(size_t)NZROWS * 3072];
__device__ __nv_bfloat16 g_zlo[(size_t)NZROWS * 3072];
__device__ __nv_bfloat16 g_whi[(size_t)MDIM * KDIM];
__device__ __nv_bfloat16 g_wlo[(size_t)MDIM * KDIM];
__device__ float g_q[(size_t)BB * CC * LL];
__device__ float g_k[(size_t)BB * CC * LL];
__device__ float g_v[(size_t)BB * CC * LL];
__device__ float g_Qr[(size_t)BB * LL * CC];
__device__ float g_Kr[(size_t)BB * LL * CC];
__device__ float g_att[(size_t)BB * LL * LL];
__device__ float g_y[(size_t)BB * CC * LL];
__device__ float g_coeff[4 * CC];
__device__ float g_off[4 * CC];

// ---------------- helpers ----------------
__device__ __forceinline__ uint32_t s2u(const void* p) {
    uint32_t a;
    asm("{ .reg .u64 t; cvta.to.shared.u64 t, %1; cvt.u32.u64 %0, t; }" : "=r"(a) : "l"(p));
    return a;
}
#define CPA16(dst, src) \
    asm volatile("cp.async.cg.shared.global [%0], [%1], 16;" :: "r"(dst), "l"(src) : "memory")

__device__ __forceinline__ void ldsm4(uint32_t* r, uint32_t addr) {
    asm volatile("ldmatrix.sync.aligned.m8n8.x4.shared.b16 {%0,%1,%2,%3}, [%4];"
                 : "=r"(r[0]), "=r"(r[1]), "=r"(r[2]), "=r"(r[3]) : "r"(addr));
}
__device__ __forceinline__ void mma16816(float* c, const uint32_t* a, const uint32_t* b) {
    asm volatile(
        "mma.sync.aligned.m16n8k16.row.col.f32.bf16.bf16.f32 "
        "{%0,%1,%2,%3}, {%4,%5,%6,%7}, {%8,%9}, {%0,%1,%2,%3};"
        : "+f"(c[0]), "+f"(c[1]), "+f"(c[2]), "+f"(c[3])
        : "r"(a[0]), "r"(a[1]), "r"(a[2]), "r"(a[3]), "r"(b[0]), "r"(b[1]));
}

// ---------------- prep: zero pad rows ----------------
__global__ void zero_pads() {
    int idx = blockIdx.x * blockDim.x + threadIdx.x;
    if (idx >= 196 * 3072) return;
    int rid = idx / 3072, c = idx - rid * 3072;
    int row;
    if (rid < 192) {
        int b = rid / 3, s = rid % 3;
        row = b * NROW + (s == 0 ? 0 : (s == 1 ? 198 : 199));
    } else {
        row = NP + (rid - 192);
    }
    size_t o = (size_t)row * 3072 + c;
    g_zhi[o] = __float2bfloat16(0.f);
    g_zlo[o] = __float2bfloat16(0.f);
}

// ---------------- prep: Chebyshev basis, bf16 hi/lo split ----------------
__global__ void build_zT(const float* __restrict__ x) {
    int idx = blockIdx.x * blockDim.x + threadIdx.x;
    if (idx >= BB * CC * LL) return;
    int l = idx % LL;
    int bc = idx / LL;
    int c = bc % CC;
    int b = bc / CC;
    float t = tanhf(x[idx]);
    float T[4];
    T[0] = 1.f; T[1] = t; T[2] = 2.f * t * t - 1.f; T[3] = 2.f * t * T[2] - t;
    size_t base = ((size_t)(b * NROW + l + 1)) * 3072 + c * 4;
    #pragma unroll
    for (int d = 0; d < 4; d++) {
        __nv_bfloat16 hi = __float2bfloat16(T[d]);
        g_zhi[base + d] = hi;
        g_zlo[base + d] = __float2bfloat16(T[d] - __bfloat162float(hi));
    }
}

// ---------------- prep: weight transpose + split ----------------
__global__ void build_W(const float* __restrict__ W, int which) {
    int idx = blockIdx.x * blockDim.x + threadIdx.x;
    if (idx >= CC * KDIM) return;
    int k = idx % KDIM;
    int co = idx / KDIM;
    int tap = k / 3072, ci = k - tap * 3072;
    float v = W[(size_t)co * (3072 * 3) + (size_t)ci * 3 + tap];
    size_t o = (size_t)(which * CC + co) * KDIM + k;
    __nv_bfloat16 hi = __float2bfloat16(v);
    g_whi[o] = hi;
    g_wlo[o] = __float2bfloat16(v - __bfloat162float(hi));
}

// ---------------- fused bf16x3 HMMA conv-GEMM ----------------
__global__ void __launch_bounds__(256, 1)
conv_mma() {
    extern __shared__ char smem[];
    uint32_t sb = s2u(smem);
    int tid = threadIdx.x, wid = tid >> 5, lane = tid & 31;
    int m0 = blockIdx.x * 128;
    int n0 = blockIdx.y * 256;
    int which = m0 / CC;
    int co0 = m0 - which * CC;

    int wm = wid & 1;       // 2 warp rows (M)
    int wn = wid >> 1;      // 4 warp cols (N)

    float acc[4][8][4];
    #pragma unroll
    for (int mt = 0; mt < 4; mt++)
        #pragma unroll
        for (int nt = 0; nt < 8; nt++)
            #pragma unroll
            for (int e = 0; e < 4; e++) acc[mt][nt][e] = 0.f;

    auto load_chunk = [&](int c, int s) {
        int tap = c / 96;
        int koff = (c - tap * 96) * 32;
        uint32_t st = sb + s * STG_BYTES;
        size_t kbase = (size_t)tap * 3072 + koff;
        // A: 128 rows x 4 chunks x 2 arrays = 1024 cp16 -> 4/thread
        #pragma unroll
        for (int i = 0; i < 4; i++) {
            int idx = tid + 256 * i;
            int row = idx >> 3, sub = idx & 7;
            int arr = sub >> 2, j = sub & 3;
            const __nv_bfloat16* src =
                (arr ? g_wlo : g_whi) + (size_t)(m0 + row) * KDIM + kbase + j * 8;
            CPA16(st + arr * A_BYTES + row * RSTRIDE + j * 16, src);
        }
        // B: 256 rows x 4 x 2 = 2048 -> 8/thread
        #pragma unroll
        for (int i = 0; i < 8; i++) {
            int idx = tid + 256 * i;
            int row = idx >> 3, sub = idx & 7;
            int arr = sub >> 2, j = sub & 3;
            const __nv_bfloat16* src =
                (arr ? g_zlo : g_zhi) + (size_t)(n0 + row + tap) * 3072 + koff + j * 8;
            CPA16(st + 2 * A_BYTES + arr * B_BYTES + row * RSTRIDE + j * 16, src);
        }
    };

    load_chunk(0, 0);
    asm volatile("cp.async.commit_group;" ::: "memory");
    load_chunk(1, 1);
    asm volatile("cp.async.commit_group;" ::: "memory");

    int g = lane >> 3, r = lane & 7;

    for (int c = 0; c < NCHUNK; c++) {
        int s = c % 3;
        asm volatile("cp.async.wait_group 1;" ::: "memory");
        __syncthreads();

        uint32_t stg = sb + s * STG_BYTES;
        #pragma unroll
        for (int ks = 0; ks < 2; ks++) {
            // A fragments: 4 m-tiles, hi+lo
            uint32_t ah[4][4], al[4][4];
            #pragma unroll
            for (int mt = 0; mt < 4; mt++) {
                uint32_t arow = (uint32_t)(wm * 64 + mt * 16 + r + (g & 1) * 8);
                uint32_t acol = (uint32_t)((2 * ks + (g >> 1)) * 16);
                ldsm4(ah[mt], stg + arow * RSTRIDE + acol);
                ldsm4(al[mt], stg + A_BYTES + arow * RSTRIDE + acol);
            }
            uint32_t bbase_hi = stg + 2 * A_BYTES;
            uint32_t bbase_lo = bbase_hi + B_BYTES;
            #pragma unroll
            for (int np = 0; np < 4; np++) {
                uint32_t brow = (uint32_t)(wn * 64 + np * 16 + (g >> 1) * 8 + r);
                uint32_t bcol = (uint32_t)((2 * ks + (g & 1)) * 16);
                uint32_t bh[4], bl[4];
                ldsm4(bh, bbase_hi + brow * RSTRIDE + bcol);
                ldsm4(bl, bbase_lo + brow * RSTRIDE + bcol);
                #pragma unroll
                for (int mt = 0; mt < 4; mt++) {
                    mma16816(acc[mt][2 * np],     ah[mt], &bh[0]);
                    mma16816(acc[mt][2 * np + 1], ah[mt], &bh[2]);
                    mma16816(acc[mt][2 * np],     ah[mt], &bl[0]);
                    mma16816(acc[mt][2 * np + 1], ah[mt], &bl[2]);
                    mma16816(acc[mt][2 * np],     al[mt], &bh[0]);
                    mma16816(acc[mt][2 * np + 1], al[mt], &bh[2]);
                }
            }
        }
        if (c + 2 < NCHUNK) load_chunk(c + 2, (c + 2) % 3);
        asm volatile("cp.async.commit_group;" ::: "memory");
    }

    // epilogue: direct scatter to q/k/v layout [b][co][l]
    float* outp = (which == 0) ? g_q : (which == 1) ? g_k : g_v;
    int lrow = lane >> 2, lcol = (lane & 3) * 2;
    #pragma unroll
    for (int mt = 0; mt < 4; mt++) {
        int m_lo = wm * 64 + mt * 16 + lrow;
        #pragma unroll
        for (int nt = 0; nt < 8; nt++) {
            int ncol = n0 + wn * 64 + nt * 8 + lcol;
            #pragma unroll
            for (int e = 0; e < 4; e++) {
                int m = m_lo + (e >> 1) * 8;
                int n = ncol + (e & 1);
                int b = n / NROW;
                int l = n - b * NROW;
                if (l < LL)
                    outp[((size_t)b * CC + (co0 + m)) * LL + l] = acc[mt][nt][e];
            }
        }
    }
}

// ---------------- BN stats -> folded coeff/off ----------------
__global__ void bn_stats(int sel, const float* __restrict__ scale, const float* __restrict__ bias) {
    const float* in = (sel == 0) ? g_q : (sel == 1) ? g_k : (sel == 2) ? g_v : g_y;
    int c = blockIdx.x;
    float s = 0.f, s2 = 0.f;
    for (int i = threadIdx.x; i < NBL; i += 256) {
        int b = i / LL, l = i - b * LL;
        float v = in[((size_t)b * CC + c) * LL + l];
        s += v; s2 += v * v;
    }
    __shared__ float sh[256], sh2[256];
    sh[threadIdx.x] = s; sh2[threadIdx.x] = s2;
    __syncthreads();
    for (int st = 128; st > 0; st >>= 1) {
        if (threadIdx.x < st) { sh[threadIdx.x] += sh[threadIdx.x + st]; sh2[threadIdx.x] += sh2[threadIdx.x + st]; }
        __syncthreads();
    }
    if (threadIdx.x == 0) {
        float m = sh[0] / (float)NBL;
        float var = sh2[0] / (float)NBL - m * m;
        float cf = scale[c] * rsqrtf(var + EPSV);
        g_coeff[sel * CC + c] = cf;
        g_off[sel * CC + c]   = bias[c] - m * cf;
    }
}

// ---------------- BN + transpose + RoPE for Q,K ----------------
__global__ void rope_kernel(const float* __restrict__ freqs) {
    int b  = blockIdx.z;
    int c0 = blockIdx.y * 64;
    int l0 = blockIdx.x * 32;
    __shared__ float s[64][33];
    for (int which = 0; which < 2; which++) {
        const float* src = which ? g_k : g_q;
        const float* cf  = g_coeff + which * CC;
        const float* of  = g_off   + which * CC;
        float* dst = which ? g_Kr : g_Qr;
        for (int t = threadIdx.x; t < 64 * 32; t += 256) {
            int cl = t / 32, ll = t - cl * 32;
            int c = c0 + cl, l = l0 + ll;
            float v = 0.f;
            if (l < LL) v = src[((size_t)b * CC + c) * LL + l] * cf[c] + of[c];
            s[cl][ll] = v;
        }
        __syncthreads();
        for (int t = threadIdx.x; t < 32 * 32; t += 256) {
            int ll = t / 32, dl = t - ll * 32;
            int l = l0 + ll;
            if (l < LL) {
                int d = c0 / 2 + dl;
                float a  = s[2 * dl][ll];
                float bb = s[2 * dl + 1][ll];
                float ra, rb;
                if (l == 0) { ra = a; rb = bb; }
                else {
                    float nf = (float)(l - 1);
                    float tx = fmodf(nf, 14.0f);
                    float ty = floorf(nf / 14.0f);
                    float ang = tx * freqs[d] + ty * freqs[384 + d];
                    float sn, cs;
                    sincosf(ang, &sn, &cs);
                    ra = a * cs - bb * sn;
                    rb = a * sn + bb * cs;
                }
                size_t o = ((size_t)b * LL + l) * CC + c0 + 2 * dl;
                dst[o] = ra; dst[o + 1] = rb;
            }
        }
        __syncthreads();
    }
}

// ---------------- energy GEMM ----------------
__global__ void energy_gemm() {
    int b = blockIdx.z;
    int i0 = blockIdx.y * 64, j0 = blockIdx.x * 64;
    __shared__ float As[16][68], Bs[16][68];
    const float* Qb = g_Qr + (size_t)b * LL * CC;
    const float* Kb = g_Kr + (size_t)b * LL * CC;
    int tid = threadIdx.x;
    int tm = tid / 16, tn = tid & 15;
    float acc[4][4];
    #pragma unroll
    for (int m = 0; m < 4; m++) for (int n = 0; n < 4; n++) acc[m][n] = 0.f;

    int r = tid >> 2, u = tid & 3;
    for (int k0 = 0; k0 < CC; k0 += 16) {
        float4 qv = make_float4(0,0,0,0), kv = make_float4(0,0,0,0);
        if (i0 + r < LL) qv = *reinterpret_cast<const float4*>(Qb + (size_t)(i0 + r) * CC + k0 + u * 4);
        if (j0 + r < LL) kv = *reinterpret_cast<const float4*>(Kb + (size_t)(j0 + r) * CC + k0 + u * 4);
        As[u*4+0][r]=qv.x; As[u*4+1][r]=qv.y; As[u*4+2][r]=qv.z; As[u*4+3][r]=qv.w;
        Bs[u*4+0][r]=kv.x; Bs[u*4+1][r]=kv.y; Bs[u*4+2][r]=kv.z; Bs[u*4+3][r]=kv.w;
        __syncthreads();
        #pragma unroll
        for (int kk = 0; kk < 16; kk++) {
            float4 a4 = *reinterpret_cast<const float4*>(&As[kk][tm * 4]);
            float4 b4 = *reinterpret_cast<const float4*>(&Bs[kk][tn * 4]);
            float a[4] = {a4.x, a4.y, a4.z, a4.w};
            float bb[4] = {b4.x, b4.y, b4.z, b4.w};
            #pragma unroll
            for (int m = 0; m < 4; m++)
                #pragma unroll
                for (int n = 0; n < 4; n++) acc[m][n] += a[m] * bb[n];
        }
        __syncthreads();
    }
    #pragma unroll
    for (int m = 0; m < 4; m++) {
        int i = i0 + tm * 4 + m;
        #pragma unroll
        for (int n = 0; n < 4; n++) {
            int j = j0 + tn * 4 + n;
            if (i < LL && j < LL) g_att[((size_t)b * LL + i) * LL + j] = acc[m][n];
        }
    }
}

// ---------------- softmax ----------------
__global__ void softmax_kernel() {
    int row = blockIdx.x * blockDim.y + threadIdx.y;
    if (row >= NBL) return;
    float* e = g_att + (size_t)row * LL;
    int lane = threadIdx.x;
    float mx = -1e30f;
    for (int j = lane; j < LL; j += 32) mx = fmaxf(mx, e[j]);
    #pragma unroll
    for (int o = 16; o; o >>= 1) mx = fmaxf(mx, __shfl_xor_sync(0xffffffffu, mx, o));
    float s = 0.f;
    for (int j = lane; j < LL; j += 32) { float v = __expf(e[j] - mx); e[j] = v; s += v; }
    #pragma unroll
    for (int o = 16; o; o >>= 1) s += __shfl_xor_sync(0xffffffffu, s, o);
    float inv = 1.f / s;
    for (int j = lane; j < LL; j += 32) e[j] *= inv;
}

// ---------------- out GEMM + residual ----------------
__global__ void out_gemm(const float* __restrict__ x, const float* __restrict__ gamma) {
    int b = blockIdx.z;
    int c0 = blockIdx.y * 64, i0 = blockIdx.x * 64;
    __shared__ float As[16][68], Bs[16][68];
    int tid = threadIdx.x;
    int tm = tid / 16, tn = tid & 15;
    float acc[4][4];
    #pragma unroll
    for (int m = 0; m < 4; m++) for (int n = 0; n < 4; n++) acc[m][n] = 0.f;

    int r = tid >> 2, u = tid & 3;
    const float* vb = g_v + (size_t)b * CC * LL;
    const float* ab = g_att + (size_t)b * LL * LL;
    int cA = c0 + r;
    float cf = g_coeff[2 * CC + cA];
    float of = g_off[2 * CC + cA];

    for (int k0 = 0; k0 < LL; k0 += 16) {
        #pragma unroll
        for (int w = 0; w < 4; w++) {
            int j = k0 + u * 4 + w;
            float av = 0.f, bv = 0.f;
            if (j < LL) {
                av = vb[(size_t)cA * LL + j] * cf + of;
                if (i0 + r < LL) bv = ab[(size_t)(i0 + r) * LL + j];
            }
            As[u*4+w][r] = av;
            Bs[u*4+w][r] = bv;
        }
        __syncthreads();
        #pragma unroll
        for (int kk = 0; kk < 16; kk++) {
            float4 a4 = *reinterpret_cast<const float4*>(&As[kk][tm * 4]);
            float4 b4 = *reinterpret_cast<const float4*>(&Bs[kk][tn * 4]);
            float a[4] = {a4.x, a4.y, a4.z, a4.w};
            float bb[4] = {b4.x, b4.y, b4.z, b4.w};
            #pragma unroll
            for (int m = 0; m < 4; m++)
                #pragma unroll
                for (int n = 0; n < 4; n++) acc[m][n] += a[m] * bb[n];
        }
        __syncthreads();
    }
    float g0 = gamma[0];
    #pragma unroll
    for (int m = 0; m < 4; m++) {
        int c = c0 + tm * 4 + m;
        #pragma unroll
        for (int n = 0; n < 4; n++) {
            int i = i0 + tn * 4 + n;
            if (i < LL) {
                size_t o = ((size_t)b * CC + c) * LL + i;
                g_y[o] = g0 * x[o] + acc[m][n];
            }
        }
    }
}

// ---------------- final normalize ----------------
__global__ void final_norm(float* __restrict__ out) {
    int idx = blockIdx.x * blockDim.x + threadIdx.x;
    if (idx >= BB * CC * LL) return;
    int c = (idx / LL) % CC;
    out[idx] = g_y[idx] * g_coeff[3 * CC + c] + g_off[3 * CC + c];
}

// ---------------- launch ----------------
extern "C" void kernel_launch(void* const* d_in, const int* in_sizes, int n_in,
                              void* d_out, int out_size) {
    const float* x      = (const float*)d_in[0];
    const float* Wq     = (const float*)d_in[1];
    const float* Wk     = (const float*)d_in[2];
    const float* Wv     = (const float*)d_in[3];
    const float* bnq_s  = (const float*)d_in[4];
    const float* bnq_b  = (const float*)d_in[5];
    const float* bnk_s  = (const float*)d_in[6];
    const float* bnk_b  = (const float*)d_in[7];
    const float* bnv_s  = (const float*)d_in[8];
    const float* bnv_b  = (const float*)d_in[9];
    const float* gamma  = (const float*)d_in[10];
    const float* freqs  = (const float*)d_in[11];
    const float* norm_s = (const float*)d_in[12];
    const float* norm_b = (const float*)d_in[13];
    float* out = (float*)d_out;

    cudaFuncSetAttribute(conv_mma, cudaFuncAttributeMaxDynamicSharedMemorySize, SMEMSZ);

    zero_pads<<<(196 * 3072 + 255) / 256, 256>>>();
    build_zT<<<(BB * CC * LL + 255) / 256, 256>>>(x);
    build_W<<<(CC * KDIM + 255) / 256, 256>>>(Wq, 0);
    build_W<<<(CC * KDIM + 255) / 256, 256>>>(Wk, 1);
    build_W<<<(CC * KDIM + 255) / 256, 256>>>(Wv, 2);
    conv_mma<<<dim3(MDIM / 128, NP / 256), 256, SMEMSZ>>>();
    bn_stats<<<CC, 256>>>(0, bnq_s, bnq_b);
    bn_stats<<<CC, 256>>>(1, bnk_s, bnk_b);
    bn_stats<<<CC, 256>>>(2, bnv_s, bnv_b);
    rope_kernel<<<dim3(7, 12, BB), 256>>>(freqs);
    energy_gemm<<<dim3(4, 4, BB), 256>>>();
    softmax_kernel<<<dim3((NBL + 3) / 4), dim3(32, 4)>>>();
    out_gemm<<<dim3(4, 12, BB), 256>>>(x, gamma);
    bn_stats<<<CC, 256>>>(3, norm_s, norm_b);
    final_norm<<<(BB * CC * LL + 255) / 256, 256>>>(out);
}

// round 5
// speedup vs baseline: 5.9545x; 1.2822x over previous
#include <cuda_runtime.h>
#include <cuda_bf16.h>
#include <math.h>
#include <stdint.h>

#define BB 64
#define CC 768
#define LL 197
#define NBL (BB*LL)
#define EPSV 1e-5f

// fused conv-GEMM geometry (degree-0 removed: 3 taps * 2304 channels)
#define MDIM 2304          // 3 proj * 768
#define KDIM 6912          // 3 taps * 2304
#define KCH  2304          // channels per tap (deg 1..3)
#define NROW 200           // padded rows per batch in zT
#define NP   (BB*NROW)     // 12800
#define NZROWS (NP+4)
#define NCHUNK 216         // KDIM/32
#define RSTRIDE 80         // smem row stride bytes (64B data + 16B pad)
#define A_BYTES (128*RSTRIDE)
#define B_BYTES (256*RSTRIDE)
#define STG_BYTES (2*A_BYTES + 2*B_BYTES)  // 61440
#define SMEMSZ (3*STG_BYTES)               // 184320

// ---------------- static device scratch ----------------
__device__ __nv_bfloat16 g_zhi[(size_t)NZROWS * KCH];
__device__ __nv_bfloat16 g_zlo[(size_t)NZROWS * KCH];
__device__ __nv_bfloat16 g_whi[(size_t)MDIM * KDIM];
__device__ __nv_bfloat16 g_wlo[(size_t)MDIM * KDIM];
__device__ float g_bias[3][MDIM];            // per-tap T0 sums s_t[m]
__device__ float g_q[(size_t)BB * CC * LL];
__device__ float g_k[(size_t)BB * CC * LL];
__device__ float g_v[(size_t)BB * CC * LL];
__device__ float g_Qr[(size_t)BB * LL * CC];
__device__ float g_Kr[(size_t)BB * LL * CC];
__device__ float g_att[(size_t)BB * LL * LL];
__device__ float g_y[(size_t)BB * CC * LL];
__device__ float g_coeff[4 * CC];
__device__ float g_off[4 * CC];

// ---------------- helpers ----------------
__device__ __forceinline__ uint32_t s2u(const void* p) {
    uint32_t a;
    asm("{ .reg .u64 t; cvta.to.shared.u64 t, %1; cvt.u32.u64 %0, t; }" : "=r"(a) : "l"(p));
    return a;
}
#define CPA16(dst, src) \
    asm volatile("cp.async.cg.shared.global [%0], [%1], 16;" :: "r"(dst), "l"(src) : "memory")

__device__ __forceinline__ void ldsm4(uint32_t* r, uint32_t addr) {
    asm volatile("ldmatrix.sync.aligned.m8n8.x4.shared.b16 {%0,%1,%2,%3}, [%4];"
                 : "=r"(r[0]), "=r"(r[1]), "=r"(r[2]), "=r"(r[3]) : "r"(addr));
}
__device__ __forceinline__ void mma16816(float* c, const uint32_t* a, const uint32_t* b) {
    asm volatile(
        "mma.sync.aligned.m16n8k16.row.col.f32.bf16.bf16.f32 "
        "{%0,%1,%2,%3}, {%4,%5,%6,%7}, {%8,%9}, {%0,%1,%2,%3};"
        : "+f"(c[0]), "+f"(c[1]), "+f"(c[2]), "+f"(c[3])
        : "r"(a[0]), "r"(a[1]), "r"(a[2]), "r"(a[3]), "r"(b[0]), "r"(b[1]));
}

// ---------------- prep: zero pad rows ----------------
__global__ void zero_pads() {
    int idx = blockIdx.x * blockDim.x + threadIdx.x;
    if (idx >= 196 * KCH) return;
    int rid = idx / KCH, c = idx - rid * KCH;
    int row;
    if (rid < 192) {
        int b = rid / 3, s = rid % 3;
        row = b * NROW + (s == 0 ? 0 : (s == 1 ? 198 : 199));
    } else {
        row = NP + (rid - 192);
    }
    size_t o = (size_t)row * KCH + c;
    g_zhi[o] = __float2bfloat16(0.f);
    g_zlo[o] = __float2bfloat16(0.f);
}

// ---------------- prep: Chebyshev basis (deg 1..3), bf16 hi/lo split ----------------
__global__ void build_zT(const float* __restrict__ x) {
    int idx = blockIdx.x * blockDim.x + threadIdx.x;
    if (idx >= BB * CC * LL) return;
    int l = idx % LL;
    int bc = idx / LL;
    int c = bc % CC;
    int b = bc / CC;
    float t = tanhf(x[idx]);
    float T[3];
    T[0] = t; T[1] = 2.f * t * t - 1.f; T[2] = 2.f * t * T[1] - t;
    size_t base = ((size_t)(b * NROW + l + 1)) * KCH + c * 3;
    #pragma unroll
    for (int d = 0; d < 3; d++) {
        __nv_bfloat16 hi = __float2bfloat16(T[d]);
        g_zhi[base + d] = hi;
        g_zlo[base + d] = __float2bfloat16(T[d] - __bfloat162float(hi));
    }
}

// ---------------- prep: weight transpose + split (deg 1..3 only) ----------------
__global__ void build_W_all(const float* __restrict__ Wq, const float* __restrict__ Wk,
                            const float* __restrict__ Wv) {
    int idx = blockIdx.x * blockDim.x + threadIdx.x;
    if (idx >= MDIM * KDIM) return;
    int k = idx % KDIM;
    int gm = idx / KDIM;
    int which = gm / CC, co = gm - which * CC;
    const float* W = (which == 0) ? Wq : (which == 1) ? Wk : Wv;
    int tap = k / KCH, rem = k - tap * KCH;
    int ci = rem / 3, d = rem - ci * 3 + 1;
    float v = W[(size_t)co * (3072 * 3) + (size_t)(ci * 4 + d) * 3 + tap];
    size_t o = (size_t)gm * KDIM + k;
    __nv_bfloat16 hi = __float2bfloat16(v);
    g_whi[o] = hi;
    g_wlo[o] = __float2bfloat16(v - __bfloat162float(hi));
}

// ---------------- prep: per-tap T0 bias sums ----------------
__global__ void build_bias(const float* __restrict__ Wq, const float* __restrict__ Wk,
                           const float* __restrict__ Wv) {
    int gm = blockIdx.x;                 // 0..2303
    int which = gm / CC, co = gm - which * CC;
    const float* W = (which == 0) ? Wq : (which == 1) ? Wk : Wv;
    int tid = threadIdx.x;               // 96 threads: 3 taps x 32 lanes
    int tap = tid >> 5, lane = tid & 31;
    float s = 0.f;
    for (int ci = lane; ci < CC; ci += 32)
        s += W[(size_t)co * (3072 * 3) + (size_t)(ci * 4) * 3 + tap];
    #pragma unroll
    for (int o = 16; o; o >>= 1) s += __shfl_xor_sync(0xffffffffu, s, o);
    if (lane == 0) g_bias[tap][gm] = s;
}

// ---------------- fused bf16x3 HMMA conv-GEMM (K=6912) ----------------
__global__ void __launch_bounds__(256, 1)
conv_mma() {
    extern __shared__ char smem[];
    uint32_t sb = s2u(smem);
    int tid = threadIdx.x, wid = tid >> 5, lane = tid & 31;
    int m0 = blockIdx.x * 128;
    int n0 = blockIdx.y * 256;
    int which = m0 / CC;
    int co0 = m0 - which * CC;

    int wm = wid & 1;
    int wn = wid >> 1;

    float acc[4][8][4];
    #pragma unroll
    for (int mt = 0; mt < 4; mt++)
        #pragma unroll
        for (int nt = 0; nt < 8; nt++)
            #pragma unroll
            for (int e = 0; e < 4; e++) acc[mt][nt][e] = 0.f;

    auto load_chunk = [&](int c, int s) {
        int tap = c / 72;
        int koff = (c - tap * 72) * 32;
        uint32_t st = sb + s * STG_BYTES;
        size_t kbase = (size_t)tap * KCH + koff;
        #pragma unroll
        for (int i = 0; i < 4; i++) {
            int idx = tid + 256 * i;
            int row = idx >> 3, sub = idx & 7;
            int arr = sub >> 2, j = sub & 3;
            const __nv_bfloat16* src =
                (arr ? g_wlo : g_whi) + (size_t)(m0 + row) * KDIM + kbase + j * 8;
            CPA16(st + arr * A_BYTES + row * RSTRIDE + j * 16, src);
        }
        #pragma unroll
        for (int i = 0; i < 8; i++) {
            int idx = tid + 256 * i;
            int row = idx >> 3, sub = idx & 7;
            int arr = sub >> 2, j = sub & 3;
            const __nv_bfloat16* src =
                (arr ? g_zlo : g_zhi) + (size_t)(n0 + row + tap) * KCH + koff + j * 8;
            CPA16(st + 2 * A_BYTES + arr * B_BYTES + row * RSTRIDE + j * 16, src);
        }
    };

    load_chunk(0, 0);
    asm volatile("cp.async.commit_group;" ::: "memory");
    load_chunk(1, 1);
    asm volatile("cp.async.commit_group;" ::: "memory");

    int g = lane >> 3, r = lane & 7;

    for (int c = 0; c < NCHUNK; c++) {
        int s = c % 3;
        asm volatile("cp.async.wait_group 1;" ::: "memory");
        __syncthreads();

        uint32_t stg = sb + s * STG_BYTES;
        #pragma unroll
        for (int ks = 0; ks < 2; ks++) {
            uint32_t ah[4][4], al[4][4];
            #pragma unroll
            for (int mt = 0; mt < 4; mt++) {
                uint32_t arow = (uint32_t)(wm * 64 + mt * 16 + r + (g & 1) * 8);
                uint32_t acol = (uint32_t)((2 * ks + (g >> 1)) * 16);
                ldsm4(ah[mt], stg + arow * RSTRIDE + acol);
                ldsm4(al[mt], stg + A_BYTES + arow * RSTRIDE + acol);
            }
            uint32_t bbase_hi = stg + 2 * A_BYTES;
            uint32_t bbase_lo = bbase_hi + B_BYTES;
            #pragma unroll
            for (int np = 0; np < 4; np++) {
                uint32_t brow = (uint32_t)(wn * 64 + np * 16 + (g >> 1) * 8 + r);
                uint32_t bcol = (uint32_t)((2 * ks + (g & 1)) * 16);
                uint32_t bh[4], bl[4];
                ldsm4(bh, bbase_hi + brow * RSTRIDE + bcol);
                ldsm4(bl, bbase_lo + brow * RSTRIDE + bcol);
                #pragma unroll
                for (int mt = 0; mt < 4; mt++) {
                    mma16816(acc[mt][2 * np],     ah[mt], &bh[0]);
                    mma16816(acc[mt][2 * np + 1], ah[mt], &bh[2]);
                    mma16816(acc[mt][2 * np],     ah[mt], &bl[0]);
                    mma16816(acc[mt][2 * np + 1], ah[mt], &bl[2]);
                    mma16816(acc[mt][2 * np],     al[mt], &bh[0]);
                    mma16816(acc[mt][2 * np + 1], al[mt], &bh[2]);
                }
            }
        }
        if (c + 2 < NCHUNK) load_chunk(c + 2, (c + 2) % 3);
        asm volatile("cp.async.commit_group;" ::: "memory");
    }

    // epilogue: add T0 bias, scatter to q/k/v layout [b][co][l]
    float* outp = (which == 0) ? g_q : (which == 1) ? g_k : g_v;
    int lrow = lane >> 2, lcol = (lane & 3) * 2;
    #pragma unroll
    for (int mt = 0; mt < 4; mt++) {
        int m_lo = wm * 64 + mt * 16 + lrow;
        float b0[2], b1[2], b2[2];
        #pragma unroll
        for (int h = 0; h < 2; h++) {
            int gm = m0 + m_lo + h * 8;
            b0[h] = g_bias[0][gm]; b1[h] = g_bias[1][gm]; b2[h] = g_bias[2][gm];
        }
        #pragma unroll
        for (int nt = 0; nt < 8; nt++) {
            int ncol = n0 + wn * 64 + nt * 8 + lcol;
            #pragma unroll
            for (int e = 0; e < 4; e++) {
                int h = e >> 1;
                int m = m_lo + h * 8;
                int n = ncol + (e & 1);
                int b = n / NROW;
                int l = n - b * NROW;
                if (l < LL) {
                    float bias = b0[h] + b1[h] + b2[h];
                    if (l == 0)   bias -= b0[h];
                    if (l == 196) bias -= b2[h];
                    outp[((size_t)b * CC + (co0 + m)) * LL + l] = acc[mt][nt][e] + bias;
                }
            }
        }
    }
}

// ---------------- BN stats (q,k,v fused via blockIdx.y) ----------------
__global__ void bn_stats3(const float* __restrict__ sq, const float* __restrict__ bq,
                          const float* __restrict__ sk, const float* __restrict__ bk,
                          const float* __restrict__ sv, const float* __restrict__ bv) {
    int sel = blockIdx.y;
    const float* in = (sel == 0) ? g_q : (sel == 1) ? g_k : g_v;
    const float* scale = (sel == 0) ? sq : (sel == 1) ? sk : sv;
    const float* bias  = (sel == 0) ? bq : (sel == 1) ? bk : bv;
    int c = blockIdx.x;
    float s = 0.f, s2 = 0.f;
    for (int i = threadIdx.x; i < NBL; i += 256) {
        int b = i / LL, l = i - b * LL;
        float v = in[((size_t)b * CC + c) * LL + l];
        s += v; s2 += v * v;
    }
    __shared__ float sh[256], sh2[256];
    sh[threadIdx.x] = s; sh2[threadIdx.x] = s2;
    __syncthreads();
    for (int st = 128; st > 0; st >>= 1) {
        if (threadIdx.x < st) { sh[threadIdx.x] += sh[threadIdx.x + st]; sh2[threadIdx.x] += sh2[threadIdx.x + st]; }
        __syncthreads();
    }
    if (threadIdx.x == 0) {
        float m = sh[0] / (float)NBL;
        float var = sh2[0] / (float)NBL - m * m;
        float cf = scale[c] * rsqrtf(var + EPSV);
        g_coeff[sel * CC + c] = cf;
        g_off[sel * CC + c]   = bias[c] - m * cf;
    }
}

__global__ void bn_stats(int sel, const float* __restrict__ scale, const float* __restrict__ bias) {
    const float* in = g_y;
    int c = blockIdx.x;
    float s = 0.f, s2 = 0.f;
    for (int i = threadIdx.x; i < NBL; i += 256) {
        int b = i / LL, l = i - b * LL;
        float v = in[((size_t)b * CC + c) * LL + l];
        s += v; s2 += v * v;
    }
    __shared__ float sh[256], sh2[256];
    sh[threadIdx.x] = s; sh2[threadIdx.x] = s2;
    __syncthreads();
    for (int st = 128; st > 0; st >>= 1) {
        if (threadIdx.x < st) { sh[threadIdx.x] += sh[threadIdx.x + st]; sh2[threadIdx.x] += sh2[threadIdx.x + st]; }
        __syncthreads();
    }
    if (threadIdx.x == 0) {
        float m = sh[0] / (float)NBL;
        float var = sh2[0] / (float)NBL - m * m;
        float cf = scale[c] * rsqrtf(var + EPSV);
        g_coeff[sel * CC + c] = cf;
        g_off[sel * CC + c]   = bias[c] - m * cf;
    }
}

// ---------------- BN + transpose + RoPE for Q,K ----------------
__global__ void rope_kernel(const float* __restrict__ freqs) {
    int b  = blockIdx.z;
    int c0 = blockIdx.y * 64;
    int l0 = blockIdx.x * 32;
    __shared__ float s[64][33];
    for (int which = 0; which < 2; which++) {
        const float* src = which ? g_k : g_q;
        const float* cf  = g_coeff + which * CC;
        const float* of  = g_off   + which * CC;
        float* dst = which ? g_Kr : g_Qr;
        for (int t = threadIdx.x; t < 64 * 32; t += 256) {
            int cl = t / 32, ll = t - cl * 32;
            int c = c0 + cl, l = l0 + ll;
            float v = 0.f;
            if (l < LL) v = src[((size_t)b * CC + c) * LL + l] * cf[c] + of[c];
            s[cl][ll] = v;
        }
        __syncthreads();
        for (int t = threadIdx.x; t < 32 * 32; t += 256) {
            int ll = t / 32, dl = t - ll * 32;
            int l = l0 + ll;
            if (l < LL) {
                int d = c0 / 2 + dl;
                float a  = s[2 * dl][ll];
                float bb = s[2 * dl + 1][ll];
                float ra, rb;
                if (l == 0) { ra = a; rb = bb; }
                else {
                    float nf = (float)(l - 1);
                    float tx = fmodf(nf, 14.0f);
                    float ty = floorf(nf / 14.0f);
                    float ang = tx * freqs[d] + ty * freqs[384 + d];
                    float sn, cs;
                    sincosf(ang, &sn, &cs);
                    ra = a * cs - bb * sn;
                    rb = a * sn + bb * cs;
                }
                size_t o = ((size_t)b * LL + l) * CC + c0 + 2 * dl;
                dst[o] = ra; dst[o + 1] = rb;
            }
        }
        __syncthreads();
    }
}

// ---------------- energy GEMM ----------------
__global__ void energy_gemm() {
    int b = blockIdx.z;
    int i0 = blockIdx.y * 64, j0 = blockIdx.x * 64;
    __shared__ float As[16][68], Bs[16][68];
    const float* Qb = g_Qr + (size_t)b * LL * CC;
    const float* Kb = g_Kr + (size_t)b * LL * CC;
    int tid = threadIdx.x;
    int tm = tid / 16, tn = tid & 15;
    float acc[4][4];
    #pragma unroll
    for (int m = 0; m < 4; m++) for (int n = 0; n < 4; n++) acc[m][n] = 0.f;

    int r = tid >> 2, u = tid & 3;
    for (int k0 = 0; k0 < CC; k0 += 16) {
        float4 qv = make_float4(0,0,0,0), kv = make_float4(0,0,0,0);
        if (i0 + r < LL) qv = *reinterpret_cast<const float4*>(Qb + (size_t)(i0 + r) * CC + k0 + u * 4);
        if (j0 + r < LL) kv = *reinterpret_cast<const float4*>(Kb + (size_t)(j0 + r) * CC + k0 + u * 4);
        As[u*4+0][r]=qv.x; As[u*4+1][r]=qv.y; As[u*4+2][r]=qv.z; As[u*4+3][r]=qv.w;
        Bs[u*4+0][r]=kv.x; Bs[u*4+1][r]=kv.y; Bs[u*4+2][r]=kv.z; Bs[u*4+3][r]=kv.w;
        __syncthreads();
        #pragma unroll
        for (int kk = 0; kk < 16; kk++) {
            float4 a4 = *reinterpret_cast<const float4*>(&As[kk][tm * 4]);
            float4 b4 = *reinterpret_cast<const float4*>(&Bs[kk][tn * 4]);
            float a[4] = {a4.x, a4.y, a4.z, a4.w};
            float bb[4] = {b4.x, b4.y, b4.z, b4.w};
            #pragma unroll
            for (int m = 0; m < 4; m++)
                #pragma unroll
                for (int n = 0; n < 4; n++) acc[m][n] += a[m] * bb[n];
        }
        __syncthreads();
    }
    #pragma unroll
    for (int m = 0; m < 4; m++) {
        int i = i0 + tm * 4 + m;
        #pragma unroll
        for (int n = 0; n < 4; n++) {
            int j = j0 + tn * 4 + n;
            if (i < LL && j < LL) g_att[((size_t)b * LL + i) * LL + j] = acc[m][n];
        }
    }
}

// ---------------- softmax ----------------
__global__ void softmax_kernel() {
    int row = blockIdx.x * blockDim.y + threadIdx.y;
    if (row >= NBL) return;
    float* e = g_att + (size_t)row * LL;
    int lane = threadIdx.x;
    float mx = -1e30f;
    for (int j = lane; j < LL; j += 32) mx = fmaxf(mx, e[j]);
    #pragma unroll
    for (int o = 16; o; o >>= 1) mx = fmaxf(mx, __shfl_xor_sync(0xffffffffu, mx, o));
    float s = 0.f;
    for (int j = lane; j < LL; j += 32) { float v = __expf(e[j] - mx); e[j] = v; s += v; }
    #pragma unroll
    for (int o = 16; o; o >>= 1) s += __shfl_xor_sync(0xffffffffu, s, o);
    float inv = 1.f / s;
    for (int j = lane; j < LL; j += 32) e[j] *= inv;
}

// ---------------- out GEMM + residual ----------------
__global__ void out_gemm(const float* __restrict__ x, const float* __restrict__ gamma) {
    int b = blockIdx.z;
    int c0 = blockIdx.y * 64, i0 = blockIdx.x * 64;
    __shared__ float As[16][68], Bs[16][68];
    int tid = threadIdx.x;
    int tm = tid / 16, tn = tid & 15;
    float acc[4][4];
    #pragma unroll
    for (int m = 0; m < 4; m++) for (int n = 0; n < 4; n++) acc[m][n] = 0.f;

    int r = tid >> 2, u = tid & 3;
    const float* vb = g_v + (size_t)b * CC * LL;
    const float* ab = g_att + (size_t)b * LL * LL;
    int cA = c0 + r;
    float cf = g_coeff[2 * CC + cA];
    float of = g_off[2 * CC + cA];

    for (int k0 = 0; k0 < LL; k0 += 16) {
        #pragma unroll
        for (int w = 0; w < 4; w++) {
            int j = k0 + u * 4 + w;
            float av = 0.f, bv = 0.f;
            if (j < LL) {
                av = vb[(size_t)cA * LL + j] * cf + of;
                if (i0 + r < LL) bv = ab[(size_t)(i0 + r) * LL + j];
            }
            As[u*4+w][r] = av;
            Bs[u*4+w][r] = bv;
        }
        __syncthreads();
        #pragma unroll
        for (int kk = 0; kk < 16; kk++) {
            float4 a4 = *reinterpret_cast<const float4*>(&As[kk][tm * 4]);
            float4 b4 = *reinterpret_cast<const float4*>(&Bs[kk][tn * 4]);
            float a[4] = {a4.x, a4.y, a4.z, a4.w};
            float bb[4] = {b4.x, b4.y, b4.z, b4.w};
            #pragma unroll
            for (int m = 0; m < 4; m++)
                #pragma unroll
                for (int n = 0; n < 4; n++) acc[m][n] += a[m] * bb[n];
        }
        __syncthreads();
    }
    float g0 = gamma[0];
    #pragma unroll
    for (int m = 0; m < 4; m++) {
        int c = c0 + tm * 4 + m;
        #pragma unroll
        for (int n = 0; n < 4; n++) {
            int i = i0 + tn * 4 + n;
            if (i < LL) {
                size_t o = ((size_t)b * CC + c) * LL + i;
                g_y[o] = g0 * x[o] + acc[m][n];
            }
        }
    }
}

// ---------------- final normalize ----------------
__global__ void final_norm(float* __restrict__ out) {
    int idx = blockIdx.x * blockDim.x + threadIdx.x;
    if (idx >= BB * CC * LL) return;
    int c = (idx / LL) % CC;
    out[idx] = g_y[idx] * g_coeff[3 * CC + c] + g_off[3 * CC + c];
}

// ---------------- launch ----------------
extern "C" void kernel_launch(void* const* d_in, const int* in_sizes, int n_in,
                              void* d_out, int out_size) {
    const float* x      = (const float*)d_in[0];
    const float* Wq     = (const float*)d_in[1];
    const float* Wk     = (const float*)d_in[2];
    const float* Wv     = (const float*)d_in[3];
    const float* bnq_s  = (const float*)d_in[4];
    const float* bnq_b  = (const float*)d_in[5];
    const float* bnk_s  = (const float*)d_in[6];
    const float* bnk_b  = (const float*)d_in[7];
    const float* bnv_s  = (const float*)d_in[8];
    const float* bnv_b  = (const float*)d_in[9];
    const float* gamma  = (const float*)d_in[10];
    const float* freqs  = (const float*)d_in[11];
    const float* norm_s = (const float*)d_in[12];
    const float* norm_b = (const float*)d_in[13];
    float* out = (float*)d_out;

    cudaFuncSetAttribute(conv_mma, cudaFuncAttributeMaxDynamicSharedMemorySize, SMEMSZ);

    zero_pads<<<(196 * KCH + 255) / 256, 256>>>();
    build_zT<<<(BB * CC * LL + 255) / 256, 256>>>(x);
    build_W_all<<<(MDIM * KDIM + 255) / 256, 256>>>(Wq, Wk, Wv);
    build_bias<<<MDIM, 96>>>(Wq, Wk, Wv);
    conv_mma<<<dim3(MDIM / 128, NP / 256), 256, SMEMSZ>>>();
    bn_stats3<<<dim3(CC, 3), 256>>>(bnq_s, bnq_b, bnk_s, bnk_b, bnv_s, bnv_b);
    rope_kernel<<<dim3(7, 12, BB), 256>>>(freqs);
    energy_gemm<<<dim3(4, 4, BB), 256>>>();
    softmax_kernel<<<dim3((NBL + 3) / 4), dim3(32, 4)>>>();
    out_gemm<<<dim3(4, 12, BB), 256>>>(x, gamma);
    bn_stats<<<CC, 256>>>(3, norm_s, norm_b);
    final_norm<<<(BB * CC * LL + 255) / 256, 256>>>(out);
}

// round 7
// speedup vs baseline: 6.2955x; 1.0573x over previous
#include <cuda_runtime.h>
#include <cuda_bf16.h>
#include <math.h>
#include <stdint.h>

#define BB 64
#define CC 768
#define LL 197
#define NBL (BB*LL)
#define EPSV 1e-5f

// fused conv-GEMM geometry (degree-0 removed)
#define MDIM 2304
#define KDIM 6912
#define KCH  2304
#define NROW 200
#define NP   (BB*NROW)
#define NZROWS (NP+4)
#define NCHUNK 216
#define RSTRIDE 80
#define A_BYTES (128*RSTRIDE)
#define B_BYTES (256*RSTRIDE)
#define STG_BYTES (2*A_BYTES + 2*B_BYTES)
#define SMEMSZ (3*STG_BYTES)

// attention HMMA geometry
#define LPAD 256            // padded token rows for Q/K (bss-zero beyond 196)
#define JPAD 224            // padded j/K dim for att & vbn
#define TSTG (4*128*RSTRIDE)       // 40960: Ahi,Alo,Bhi,Blo (128x32 bf16 each)
#define TSMEM (3*TSTG)             // 122880 (3-stage ring — fixes R6 race)

// ---------------- static device scratch ----------------
__device__ __nv_bfloat16 g_zhi[(size_t)NZROWS * KCH];
__device__ __nv_bfloat16 g_zlo[(size_t)NZROWS * KCH];
__device__ __nv_bfloat16 g_whi[(size_t)MDIM * KDIM];
__device__ __nv_bfloat16 g_wlo[(size_t)MDIM * KDIM];
__device__ float g_bias[3][MDIM];
__device__ float g_q[(size_t)BB * CC * LL];
__device__ float g_k[(size_t)BB * CC * LL];
__device__ float g_v[(size_t)BB * CC * LL];
__device__ __nv_bfloat16 g_Qh[(size_t)BB * LPAD * CC];
__device__ __nv_bfloat16 g_Ql[(size_t)BB * LPAD * CC];
__device__ __nv_bfloat16 g_Kh[(size_t)BB * LPAD * CC];
__device__ __nv_bfloat16 g_Kl[(size_t)BB * LPAD * CC];
__device__ float g_att[(size_t)BB * LL * LL];
__device__ __nv_bfloat16 g_atth[(size_t)BB * LPAD * JPAD];
__device__ __nv_bfloat16 g_attl[(size_t)BB * LPAD * JPAD];
__device__ __nv_bfloat16 g_vh[(size_t)BB * CC * JPAD];
__device__ __nv_bfloat16 g_vl[(size_t)BB * CC * JPAD];
__device__ float g_y[(size_t)BB * CC * LL];
__device__ float g_coeff[4 * CC];
__device__ float g_off[4 * CC];

// ---------------- helpers ----------------
__device__ __forceinline__ uint32_t s2u(const void* p) {
    uint32_t a;
    asm("{ .reg .u64 t; cvta.to.shared.u64 t, %1; cvt.u32.u64 %0, t; }" : "=r"(a) : "l"(p));
    return a;
}
#define CPA16(dst, src) \
    asm volatile("cp.async.cg.shared.global [%0], [%1], 16;" :: "r"(dst), "l"(src) : "memory")

__device__ __forceinline__ void ldsm4(uint32_t* r, uint32_t addr) {
    asm volatile("ldmatrix.sync.aligned.m8n8.x4.shared.b16 {%0,%1,%2,%3}, [%4];"
                 : "=r"(r[0]), "=r"(r[1]), "=r"(r[2]), "=r"(r[3]) : "r"(addr));
}
__device__ __forceinline__ void mma16816(float* c, const uint32_t* a, const uint32_t* b) {
    asm volatile(
        "mma.sync.aligned.m16n8k16.row.col.f32.bf16.bf16.f32 "
        "{%0,%1,%2,%3}, {%4,%5,%6,%7}, {%8,%9}, {%0,%1,%2,%3};"
        : "+f"(c[0]), "+f"(c[1]), "+f"(c[2]), "+f"(c[3])
        : "r"(a[0]), "r"(a[1]), "r"(a[2]), "r"(a[3]), "r"(b[0]), "r"(b[1]));
}
__device__ __forceinline__ void bf16split(float v, __nv_bfloat16* hi, __nv_bfloat16* lo) {
    __nv_bfloat16 h = __float2bfloat16(v);
    *hi = h;
    *lo = __float2bfloat16(v - __bfloat162float(h));
}

// ---------------- prep kernels ----------------
__global__ void zero_pads() {
    int idx = blockIdx.x * blockDim.x + threadIdx.x;
    if (idx >= 196 * KCH) return;
    int rid = idx / KCH, c = idx - rid * KCH;
    int row;
    if (rid < 192) {
        int b = rid / 3, s = rid % 3;
        row = b * NROW + (s == 0 ? 0 : (s == 1 ? 198 : 199));
    } else {
        row = NP + (rid - 192);
    }
    size_t o = (size_t)row * KCH + c;
    g_zhi[o] = __float2bfloat16(0.f);
    g_zlo[o] = __float2bfloat16(0.f);
}

__global__ void build_zT(const float* __restrict__ x) {
    int idx = blockIdx.x * blockDim.x + threadIdx.x;
    if (idx >= BB * CC * LL) return;
    int l = idx % LL;
    int bc = idx / LL;
    int c = bc % CC;
    int b = bc / CC;
    float t = tanhf(x[idx]);
    float T[3];
    T[0] = t; T[1] = 2.f * t * t - 1.f; T[2] = 2.f * t * T[1] - t;
    size_t base = ((size_t)(b * NROW + l + 1)) * KCH + c * 3;
    #pragma unroll
    for (int d = 0; d < 3; d++)
        bf16split(T[d], &g_zhi[base + d], &g_zlo[base + d]);
}

__global__ void build_W_all(const float* __restrict__ Wq, const float* __restrict__ Wk,
                            const float* __restrict__ Wv) {
    int idx = blockIdx.x * blockDim.x + threadIdx.x;
    if (idx >= MDIM * KDIM) return;
    int k = idx % KDIM;
    int gm = idx / KDIM;
    int which = gm / CC, co = gm - which * CC;
    const float* W = (which == 0) ? Wq : (which == 1) ? Wk : Wv;
    int tap = k / KCH, rem = k - tap * KCH;
    int ci = rem / 3, d = rem - ci * 3 + 1;
    float v = W[(size_t)co * (3072 * 3) + (size_t)(ci * 4 + d) * 3 + tap];
    size_t o = (size_t)gm * KDIM + k;
    bf16split(v, &g_whi[o], &g_wlo[o]);
}

__global__ void build_bias(const float* __restrict__ Wq, const float* __restrict__ Wk,
                           const float* __restrict__ Wv) {
    int gm = blockIdx.x;
    int which = gm / CC, co = gm - which * CC;
    const float* W = (which == 0) ? Wq : (which == 1) ? Wk : Wv;
    int tid = threadIdx.x;
    int tap = tid >> 5, lane = tid & 31;
    float s = 0.f;
    for (int ci = lane; ci < CC; ci += 32)
        s += W[(size_t)co * (3072 * 3) + (size_t)(ci * 4) * 3 + tap];
    #pragma unroll
    for (int o = 16; o; o >>= 1) s += __shfl_xor_sync(0xffffffffu, s, o);
    if (lane == 0) g_bias[tap][gm] = s;
}

// ---------------- fused bf16x3 HMMA conv-GEMM ----------------
__global__ void __launch_bounds__(256, 1)
conv_mma() {
    extern __shared__ char smem[];
    uint32_t sb = s2u(smem);
    int tid = threadIdx.x, wid = tid >> 5, lane = tid & 31;
    int m0 = blockIdx.x * 128;
    int n0 = blockIdx.y * 256;
    int which = m0 / CC;
    int co0 = m0 - which * CC;
    int wm = wid & 1;
    int wn = wid >> 1;

    float acc[4][8][4];
    #pragma unroll
    for (int mt = 0; mt < 4; mt++)
        #pragma unroll
        for (int nt = 0; nt < 8; nt++)
            #pragma unroll
            for (int e = 0; e < 4; e++) acc[mt][nt][e] = 0.f;

    auto load_chunk = [&](int c, int s) {
        int tap = c / 72;
        int koff = (c - tap * 72) * 32;
        uint32_t st = sb + s * STG_BYTES;
        size_t kbase = (size_t)tap * KCH + koff;
        #pragma unroll
        for (int i = 0; i < 4; i++) {
            int idx = tid + 256 * i;
            int row = idx >> 3, sub = idx & 7;
            int arr = sub >> 2, j = sub & 3;
            const __nv_bfloat16* src =
                (arr ? g_wlo : g_whi) + (size_t)(m0 + row) * KDIM + kbase + j * 8;
            CPA16(st + arr * A_BYTES + row * RSTRIDE + j * 16, src);
        }
        #pragma unroll
        for (int i = 0; i < 8; i++) {
            int idx = tid + 256 * i;
            int row = idx >> 3, sub = idx & 7;
            int arr = sub >> 2, j = sub & 3;
            const __nv_bfloat16* src =
                (arr ? g_zlo : g_zhi) + (size_t)(n0 + row + tap) * KCH + koff + j * 8;
            CPA16(st + 2 * A_BYTES + arr * B_BYTES + row * RSTRIDE + j * 16, src);
        }
    };

    load_chunk(0, 0);
    asm volatile("cp.async.commit_group;" ::: "memory");
    load_chunk(1, 1);
    asm volatile("cp.async.commit_group;" ::: "memory");

    int g = lane >> 3, r = lane & 7;

    for (int c = 0; c < NCHUNK; c++) {
        int s = c % 3;
        asm volatile("cp.async.wait_group 1;" ::: "memory");
        __syncthreads();
        uint32_t stg = sb + s * STG_BYTES;
        #pragma unroll
        for (int ks = 0; ks < 2; ks++) {
            uint32_t ah[4][4], al[4][4];
            #pragma unroll
            for (int mt = 0; mt < 4; mt++) {
                uint32_t arow = (uint32_t)(wm * 64 + mt * 16 + r + (g & 1) * 8);
                uint32_t acol = (uint32_t)((2 * ks + (g >> 1)) * 16);
                ldsm4(ah[mt], stg + arow * RSTRIDE + acol);
                ldsm4(al[mt], stg + A_BYTES + arow * RSTRIDE + acol);
            }
            uint32_t bbase_hi = stg + 2 * A_BYTES;
            uint32_t bbase_lo = bbase_hi + B_BYTES;
            #pragma unroll
            for (int np = 0; np < 4; np++) {
                uint32_t brow = (uint32_t)(wn * 64 + np * 16 + (g >> 1) * 8 + r);
                uint32_t bcol = (uint32_t)((2 * ks + (g & 1)) * 16);
                uint32_t bh[4], bl[4];
                ldsm4(bh, bbase_hi + brow * RSTRIDE + bcol);
                ldsm4(bl, bbase_lo + brow * RSTRIDE + bcol);
                #pragma unroll
                for (int mt = 0; mt < 4; mt++) {
                    mma16816(acc[mt][2 * np],     ah[mt], &bh[0]);
                    mma16816(acc[mt][2 * np + 1], ah[mt], &bh[2]);
                    mma16816(acc[mt][2 * np],     ah[mt], &bl[0]);
                    mma16816(acc[mt][2 * np + 1], ah[mt], &bl[2]);
                    mma16816(acc[mt][2 * np],     al[mt], &bh[0]);
                    mma16816(acc[mt][2 * np + 1], al[mt], &bh[2]);
                }
            }
        }
        if (c + 2 < NCHUNK) load_chunk(c + 2, (c + 2) % 3);
        asm volatile("cp.async.commit_group;" ::: "memory");
    }

    float* outp = (which == 0) ? g_q : (which == 1) ? g_k : g_v;
    int lrow = lane >> 2, lcol = (lane & 3) * 2;
    #pragma unroll
    for (int mt = 0; mt < 4; mt++) {
        int m_lo = wm * 64 + mt * 16 + lrow;
        float b0[2], b1[2], b2[2];
        #pragma unroll
        for (int h = 0; h < 2; h++) {
            int gm = m0 + m_lo + h * 8;
            b0[h] = g_bias[0][gm]; b1[h] = g_bias[1][gm]; b2[h] = g_bias[2][gm];
        }
        #pragma unroll
        for (int nt = 0; nt < 8; nt++) {
            int ncol = n0 + wn * 64 + nt * 8 + lcol;
            #pragma unroll
            for (int e = 0; e < 4; e++) {
                int h = e >> 1;
                int m = m_lo + h * 8;
                int n = ncol + (e & 1);
                int b = n / NROW;
                int l = n - b * NROW;
                if (l < LL) {
                    float bias = b0[h] + b1[h] + b2[h];
                    if (l == 0)   bias -= b0[h];
                    if (l == 196) bias -= b2[h];
                    outp[((size_t)b * CC + (co0 + m)) * LL + l] = acc[mt][nt][e] + bias;
                }
            }
        }
    }
}

// ---------------- BN stats ----------------
__global__ void bn_stats3(const float* __restrict__ sq, const float* __restrict__ bq,
                          const float* __restrict__ sk, const float* __restrict__ bk,
                          const float* __restrict__ sv, const float* __restrict__ bv) {
    int sel = blockIdx.y;
    const float* in = (sel == 0) ? g_q : (sel == 1) ? g_k : g_v;
    const float* scale = (sel == 0) ? sq : (sel == 1) ? sk : sv;
    const float* bias  = (sel == 0) ? bq : (sel == 1) ? bk : bv;
    int c = blockIdx.x;
    float s = 0.f, s2 = 0.f;
    for (int i = threadIdx.x; i < NBL; i += 256) {
        int b = i / LL, l = i - b * LL;
        float v = in[((size_t)b * CC + c) * LL + l];
        s += v; s2 += v * v;
    }
    __shared__ float sh[256], sh2[256];
    sh[threadIdx.x] = s; sh2[threadIdx.x] = s2;
    __syncthreads();
    for (int st = 128; st > 0; st >>= 1) {
        if (threadIdx.x < st) { sh[threadIdx.x] += sh[threadIdx.x + st]; sh2[threadIdx.x] += sh2[threadIdx.x + st]; }
        __syncthreads();
    }
    if (threadIdx.x == 0) {
        float m = sh[0] / (float)NBL;
        float var = sh2[0] / (float)NBL - m * m;
        float cf = scale[c] * rsqrtf(var + EPSV);
        g_coeff[sel * CC + c] = cf;
        g_off[sel * CC + c]   = bias[c] - m * cf;
    }
}

__global__ void bn_stats(int sel, const float* __restrict__ scale, const float* __restrict__ bias) {
    const float* in = g_y;
    int c = blockIdx.x;
    float s = 0.f, s2 = 0.f;
    for (int i = threadIdx.x; i < NBL; i += 256) {
        int b = i / LL, l = i - b * LL;
        float v = in[((size_t)b * CC + c) * LL + l];
        s += v; s2 += v * v;
    }
    __shared__ float sh[256], sh2[256];
    sh[threadIdx.x] = s; sh2[threadIdx.x] = s2;
    __syncthreads();
    for (int st = 128; st > 0; st >>= 1) {
        if (threadIdx.x < st) { sh[threadIdx.x] += sh[threadIdx.x + st]; sh2[threadIdx.x] += sh2[threadIdx.x + st]; }
        __syncthreads();
    }
    if (threadIdx.x == 0) {
        float m = sh[0] / (float)NBL;
        float var = sh2[0] / (float)NBL - m * m;
        float cf = scale[c] * rsqrtf(var + EPSV);
        g_coeff[sel * CC + c] = cf;
        g_off[sel * CC + c]   = bias[c] - m * cf;
    }
}

// ---------------- BN + transpose + RoPE -> bf16 hi/lo ----------------
__global__ void rope_kernel(const float* __restrict__ freqs) {
    int b  = blockIdx.z;
    int c0 = blockIdx.y * 64;
    int l0 = blockIdx.x * 32;
    __shared__ float s[64][33];
    for (int which = 0; which < 2; which++) {
        const float* src = which ? g_k : g_q;
        const float* cf  = g_coeff + which * CC;
        const float* of  = g_off   + which * CC;
        __nv_bfloat16* dh = which ? g_Kh : g_Qh;
        __nv_bfloat16* dl = which ? g_Kl : g_Ql;
        for (int t = threadIdx.x; t < 64 * 32; t += 256) {
            int cl = t / 32, ll = t - cl * 32;
            int c = c0 + cl, l = l0 + ll;
            float v = 0.f;
            if (l < LL) v = src[((size_t)b * CC + c) * LL + l] * cf[c] + of[c];
            s[cl][ll] = v;
        }
        __syncthreads();
        for (int t = threadIdx.x; t < 32 * 32; t += 256) {
            int ll = t / 32, dl2 = t - ll * 32;
            int l = l0 + ll;
            if (l < LL) {
                int d = c0 / 2 + dl2;
                float a  = s[2 * dl2][ll];
                float bb = s[2 * dl2 + 1][ll];
                float ra, rb;
                if (l == 0) { ra = a; rb = bb; }
                else {
                    float nf = (float)(l - 1);
                    float tx = fmodf(nf, 14.0f);
                    float ty = floorf(nf / 14.0f);
                    float ang = tx * freqs[d] + ty * freqs[384 + d];
                    float sn, cs;
                    sincosf(ang, &sn, &cs);
                    ra = a * cs - bb * sn;
                    rb = a * sn + bb * cs;
                }
                size_t o = ((size_t)b * LPAD + l) * CC + c0 + 2 * dl2;
                bf16split(ra, &dh[o], &dl[o]);
                bf16split(rb, &dh[o + 1], &dl[o + 1]);
            }
        }
        __syncthreads();
    }
}

// ---------------- energy: bf16x3 HMMA (3-stage pipeline) ----------------
__global__ void __launch_bounds__(256)
energy_mma() {
    extern __shared__ char smem[];
    uint32_t sb = s2u(smem);
    int tid = threadIdx.x, wid = tid >> 5, lane = tid & 31;
    int m0 = blockIdx.x * 128;
    int n0 = blockIdx.y * 128;
    int b  = blockIdx.z;
    int wm = wid & 1;
    int wn = wid >> 1;

    const __nv_bfloat16* Ah = g_Qh + (size_t)b * LPAD * CC;
    const __nv_bfloat16* Al = g_Ql + (size_t)b * LPAD * CC;
    const __nv_bfloat16* Bh = g_Kh + (size_t)b * LPAD * CC;
    const __nv_bfloat16* Bl = g_Kl + (size_t)b * LPAD * CC;

    float acc[4][4][4];
    #pragma unroll
    for (int mt = 0; mt < 4; mt++)
        #pragma unroll
        for (int nt = 0; nt < 4; nt++)
            #pragma unroll
            for (int e = 0; e < 4; e++) acc[mt][nt][e] = 0.f;

    auto load_chunk = [&](int c, int s) {
        int k0 = c * 32;
        uint32_t st = sb + s * TSTG;
        #pragma unroll
        for (int i = 0; i < 2; i++) {
            int idx = tid + 256 * i;
            int row = idx >> 2, sub = idx & 3;
            uint32_t so = (uint32_t)(row * RSTRIDE + sub * 16);
            CPA16(st + so,             Ah + (size_t)(m0 + row) * CC + k0 + sub * 8);
            CPA16(st + A_BYTES + so,   Al + (size_t)(m0 + row) * CC + k0 + sub * 8);
            CPA16(st + 2*A_BYTES + so, Bh + (size_t)(n0 + row) * CC + k0 + sub * 8);
            CPA16(st + 3*A_BYTES + so, Bl + (size_t)(n0 + row) * CC + k0 + sub * 8);
        }
    };

    load_chunk(0, 0);
    asm volatile("cp.async.commit_group;" ::: "memory");
    load_chunk(1, 1);
    asm volatile("cp.async.commit_group;" ::: "memory");

    int g = lane >> 3, r = lane & 7;
    const int NCH = CC / 32;

    for (int c = 0; c < NCH; c++) {
        int s = c % 3;
        asm volatile("cp.async.wait_group 1;" ::: "memory");
        __syncthreads();
        uint32_t stg = sb + s * TSTG;
        #pragma unroll
        for (int ks = 0; ks < 2; ks++) {
            uint32_t ah[4][4], al[4][4];
            #pragma unroll
            for (int mt = 0; mt < 4; mt++) {
                uint32_t arow = (uint32_t)(wm * 64 + mt * 16 + r + (g & 1) * 8);
                uint32_t acol = (uint32_t)((2 * ks + (g >> 1)) * 16);
                ldsm4(ah[mt], stg + arow * RSTRIDE + acol);
                ldsm4(al[mt], stg + A_BYTES + arow * RSTRIDE + acol);
            }
            #pragma unroll
            for (int np = 0; np < 2; np++) {
                uint32_t brow = (uint32_t)(wn * 32 + np * 16 + (g >> 1) * 8 + r);
                uint32_t bcol = (uint32_t)((2 * ks + (g & 1)) * 16);
                uint32_t bh[4], bl[4];
                ldsm4(bh, stg + 2*A_BYTES + brow * RSTRIDE + bcol);
                ldsm4(bl, stg + 3*A_BYTES + brow * RSTRIDE + bcol);
                #pragma unroll
                for (int mt = 0; mt < 4; mt++) {
                    mma16816(acc[mt][2 * np],     ah[mt], &bh[0]);
                    mma16816(acc[mt][2 * np + 1], ah[mt], &bh[2]);
                    mma16816(acc[mt][2 * np],     ah[mt], &bl[0]);
                    mma16816(acc[mt][2 * np + 1], ah[mt], &bl[2]);
                    mma16816(acc[mt][2 * np],     al[mt], &bh[0]);
                    mma16816(acc[mt][2 * np + 1], al[mt], &bh[2]);
                }
            }
        }
        if (c + 2 < NCH) load_chunk(c + 2, (c + 2) % 3);
        asm volatile("cp.async.commit_group;" ::: "memory");
    }

    int lrow = lane >> 2, lcol = (lane & 3) * 2;
    float* ab = g_att + (size_t)b * LL * LL;
    #pragma unroll
    for (int mt = 0; mt < 4; mt++) {
        #pragma unroll
        for (int nt = 0; nt < 4; nt++) {
            #pragma unroll
            for (int e = 0; e < 4; e++) {
                int i = m0 + wm * 64 + mt * 16 + lrow + (e >> 1) * 8;
                int j = n0 + wn * 32 + nt * 8 + lcol + (e & 1);
                if (i < LL && j < LL) ab[(size_t)i * LL + j] = acc[mt][nt][e];
            }
        }
    }
}

// ---------------- softmax + emit bf16 hi/lo att ----------------
__global__ void softmax_kernel() {
    int row = blockIdx.x * blockDim.y + threadIdx.y;
    if (row >= NBL) return;
    int b = row / LL, i = row - b * LL;
    float* e = g_att + (size_t)row * LL;
    int lane = threadIdx.x;
    float mx = -1e30f;
    for (int j = lane; j < LL; j += 32) mx = fmaxf(mx, e[j]);
    #pragma unroll
    for (int o = 16; o; o >>= 1) mx = fmaxf(mx, __shfl_xor_sync(0xffffffffu, mx, o));
    float s = 0.f;
    for (int j = lane; j < LL; j += 32) { float v = __expf(e[j] - mx); e[j] = v; s += v; }
    #pragma unroll
    for (int o = 16; o; o >>= 1) s += __shfl_xor_sync(0xffffffffu, s, o);
    float inv = 1.f / s;
    __nv_bfloat16* ah = g_atth + ((size_t)b * LPAD + i) * JPAD;
    __nv_bfloat16* al = g_attl + ((size_t)b * LPAD + i) * JPAD;
    for (int j = lane; j < JPAD; j += 32) {
        float v = (j < LL) ? e[j] * inv : 0.f;
        bf16split(v, &ah[j], &al[j]);
    }
}

// ---------------- vbn -> bf16 hi/lo [b][c][jpad] ----------------
__global__ void vconv() {
    int idx = blockIdx.x * blockDim.x + threadIdx.x;
    if (idx >= BB * CC * JPAD) return;
    int j = idx % JPAD;
    int bc = idx / JPAD;
    int c = bc % CC;
    int b = bc / CC;
    float v = 0.f;
    if (j < LL)
        v = g_v[((size_t)b * CC + c) * LL + j] * g_coeff[2 * CC + c] + g_off[2 * CC + c];
    bf16split(v, &g_vh[idx], &g_vl[idx]);
}

// ---------------- out: bf16x3 HMMA (3-stage), y = gamma*x + V.att^T ----------------
__global__ void __launch_bounds__(256)
out_mma(const float* __restrict__ x, const float* __restrict__ gamma) {
    extern __shared__ char smem[];
    uint32_t sb = s2u(smem);
    int tid = threadIdx.x, wid = tid >> 5, lane = tid & 31;
    int m0 = blockIdx.x * 128;   // c
    int n0 = blockIdx.y * 128;   // i
    int b  = blockIdx.z;
    int wm = wid & 1;
    int wn = wid >> 1;

    const __nv_bfloat16* Ah = g_vh + (size_t)b * CC * JPAD;
    const __nv_bfloat16* Al = g_vl + (size_t)b * CC * JPAD;
    const __nv_bfloat16* Bh = g_atth + (size_t)b * LPAD * JPAD;
    const __nv_bfloat16* Bl = g_attl + (size_t)b * LPAD * JPAD;

    float acc[4][4][4];
    #pragma unroll
    for (int mt = 0; mt < 4; mt++)
        #pragma unroll
        for (int nt = 0; nt < 4; nt++)
            #pragma unroll
            for (int e = 0; e < 4; e++) acc[mt][nt][e] = 0.f;

    auto load_chunk = [&](int c, int s) {
        int k0 = c * 32;
        uint32_t st = sb + s * TSTG;
        #pragma unroll
        for (int i = 0; i < 2; i++) {
            int idx = tid + 256 * i;
            int row = idx >> 2, sub = idx & 3;
            uint32_t so = (uint32_t)(row * RSTRIDE + sub * 16);
            CPA16(st + so,             Ah + (size_t)(m0 + row) * JPAD + k0 + sub * 8);
            CPA16(st + A_BYTES + so,   Al + (size_t)(m0 + row) * JPAD + k0 + sub * 8);
            CPA16(st + 2*A_BYTES + so, Bh + (size_t)(n0 + row) * JPAD + k0 + sub * 8);
            CPA16(st + 3*A_BYTES + so, Bl + (size_t)(n0 + row) * JPAD + k0 + sub * 8);
        }
    };

    load_chunk(0, 0);
    asm volatile("cp.async.commit_group;" ::: "memory");
    load_chunk(1, 1);
    asm volatile("cp.async.commit_group;" ::: "memory");

    int g = lane >> 3, r = lane & 7;
    const int NCH = JPAD / 32;   // 7

    for (int c = 0; c < NCH; c++) {
        int s = c % 3;
        asm volatile("cp.async.wait_group 1;" ::: "memory");
        __syncthreads();
        uint32_t stg = sb + s * TSTG;
        #pragma unroll
        for (int ks = 0; ks < 2; ks++) {
            uint32_t ah[4][4], al[4][4];
            #pragma unroll
            for (int mt = 0; mt < 4; mt++) {
                uint32_t arow = (uint32_t)(wm * 64 + mt * 16 + r + (g & 1) * 8);
                uint32_t acol = (uint32_t)((2 * ks + (g >> 1)) * 16);
                ldsm4(ah[mt], stg + arow * RSTRIDE + acol);
                ldsm4(al[mt], stg + A_BYTES + arow * RSTRIDE + acol);
            }
            #pragma unroll
            for (int np = 0; np < 2; np++) {
                uint32_t brow = (uint32_t)(wn * 32 + np * 16 + (g >> 1) * 8 + r);
                uint32_t bcol = (uint32_t)((2 * ks + (g & 1)) * 16);
                uint32_t bh[4], bl[4];
                ldsm4(bh, stg + 2*A_BYTES + brow * RSTRIDE + bcol);
                ldsm4(bl, stg + 3*A_BYTES + brow * RSTRIDE + bcol);
                #pragma unroll
                for (int mt = 0; mt < 4; mt++) {
                    mma16816(acc[mt][2 * np],     ah[mt], &bh[0]);
                    mma16816(acc[mt][2 * np + 1], ah[mt], &bh[2]);
                    mma16816(acc[mt][2 * np],     ah[mt], &bl[0]);
                    mma16816(acc[mt][2 * np + 1], ah[mt], &bl[2]);
                    mma16816(acc[mt][2 * np],     al[mt], &bh[0]);
                    mma16816(acc[mt][2 * np + 1], al[mt], &bh[2]);
                }
            }
        }
        if (c + 2 < NCH) load_chunk(c + 2, (c + 2) % 3);
        asm volatile("cp.async.commit_group;" ::: "memory");
    }

    float g0 = gamma[0];
    int lrow = lane >> 2, lcol = (lane & 3) * 2;
    #pragma unroll
    for (int mt = 0; mt < 4; mt++) {
        #pragma unroll
        for (int nt = 0; nt < 4; nt++) {
            #pragma unroll
            for (int e = 0; e < 4; e++) {
                int cch = m0 + wm * 64 + mt * 16 + lrow + (e >> 1) * 8;
                int i = n0 + wn * 32 + nt * 8 + lcol + (e & 1);
                if (i < LL) {
                    size_t o = ((size_t)b * CC + cch) * LL + i;
                    g_y[o] = g0 * x[o] + acc[mt][nt][e];
                }
            }
        }
    }
}

// ---------------- final normalize ----------------
__global__ void final_norm(float* __restrict__ out) {
    int idx = blockIdx.x * blockDim.x + threadIdx.x;
    if (idx >= BB * CC * LL) return;
    int c = (idx / LL) % CC;
    out[idx] = g_y[idx] * g_coeff[3 * CC + c] + g_off[3 * CC + c];
}

// ---------------- launch ----------------
extern "C" void kernel_launch(void* const* d_in, const int* in_sizes, int n_in,
                              void* d_out, int out_size) {
    const float* x      = (const float*)d_in[0];
    const float* Wq     = (const float*)d_in[1];
    const float* Wk     = (const float*)d_in[2];
    const float* Wv     = (const float*)d_in[3];
    const float* bnq_s  = (const float*)d_in[4];
    const float* bnq_b  = (const float*)d_in[5];
    const float* bnk_s  = (const float*)d_in[6];
    const float* bnk_b  = (const float*)d_in[7];
    const float* bnv_s  = (const float*)d_in[8];
    const float* bnv_b  = (const float*)d_in[9];
    const float* gamma  = (const float*)d_in[10];
    const float* freqs  = (const float*)d_in[11];
    const float* norm_s = (const float*)d_in[12];
    const float* norm_b = (const float*)d_in[13];
    float* out = (float*)d_out;

    cudaFuncSetAttribute(conv_mma, cudaFuncAttributeMaxDynamicSharedMemorySize, SMEMSZ);
    cudaFuncSetAttribute(energy_mma, cudaFuncAttributeMaxDynamicSharedMemorySize, TSMEM);
    cudaFuncSetAttribute(out_mma, cudaFuncAttributeMaxDynamicSharedMemorySize, TSMEM);

    zero_pads<<<(196 * KCH + 255) / 256, 256>>>();
    build_zT<<<(BB * CC * LL + 255) / 256, 256>>>(x);
    build_W_all<<<(MDIM * KDIM + 255) / 256, 256>>>(Wq, Wk, Wv);
    build_bias<<<MDIM, 96>>>(Wq, Wk, Wv);
    conv_mma<<<dim3(MDIM / 128, NP / 256), 256, SMEMSZ>>>();
    bn_stats3<<<dim3(CC, 3), 256>>>(bnq_s, bnq_b, bnk_s, bnk_b, bnv_s, bnv_b);
    rope_kernel<<<dim3(7, 12, BB), 256>>>(freqs);
    vconv<<<(BB * CC * JPAD + 255) / 256, 256>>>();
    energy_mma<<<dim3(2, 2, BB), 256, TSMEM>>>();
    softmax_kernel<<<dim3((NBL + 3) / 4), dim3(32, 4)>>>();
    out_mma<<<dim3(CC / 128, 2, BB), 256, TSMEM>>>(x, gamma);
    bn_stats<<<CC, 256>>>(3, norm_s, norm_b);
    final_norm<<<(BB * CC * LL + 255) / 256, 256>>>(out);
}